// round 11
// baseline (speedup 1.0000x reference)
#include <cuda_runtime.h>
#include <cstdint>

// ---------------- problem constants ----------------
#define B_WIN    4096
#define SEQ      49
#define CDIM     192
#define NHEAD    6
#define HDIM     32
#define KD       192
#define QKV_COLS 576
#define MROWS    200704       // B_WIN * SEQ

// ---------------- scratch (__device__ globals, allocation-free) -------------
__device__ float g_qkv [(size_t)B_WIN * SEQ * QKV_COLS];
__device__ float g_attn[(size_t)B_WIN * SEQ * CDIM];
__device__ float g_bm  [64 * NHEAD * SEQ * 56];   // fused bias+mask, cols padded to 56

__device__ __forceinline__ uint32_t f2tf32(float x) {
    uint32_t r; asm("cvt.rna.tf32.f32 %0, %1;" : "=r"(r) : "f"(x)); return r;
}

__device__ __forceinline__ void mma_tf32(float* d, const uint32_t* a, const uint32_t* b) {
    asm volatile(
        "mma.sync.aligned.m16n8k8.row.col.f32.tf32.tf32.f32 "
        "{%0,%1,%2,%3}, {%4,%5,%6,%7}, {%8,%9}, {%0,%1,%2,%3};"
        : "+f"(d[0]), "+f"(d[1]), "+f"(d[2]), "+f"(d[3])
        : "r"(a[0]), "r"(a[1]), "r"(a[2]), "r"(a[3]), "r"(b[0]), "r"(b[1]));
}
__device__ __forceinline__ void mma_f(float* d, float a0, float a1, float a2, float a3,
                                      float b0, float b1) {
    asm volatile(
        "mma.sync.aligned.m16n8k8.row.col.f32.tf32.tf32.f32 "
        "{%0,%1,%2,%3}, {%4,%5,%6,%7}, {%8,%9}, {%0,%1,%2,%3};"
        : "+f"(d[0]), "+f"(d[1]), "+f"(d[2]), "+f"(d[3])
        : "r"(__float_as_uint(a0)), "r"(__float_as_uint(a1)),
          "r"(__float_as_uint(a2)), "r"(__float_as_uint(a3)),
          "r"(__float_as_uint(b0)), "r"(__float_as_uint(b1)));
}

__device__ __forceinline__ void cp16(uint32_t smem_addr, const void* gptr) {
    asm volatile("cp.async.cg.shared.global [%0], [%1], 16;"
                 :: "r"(smem_addr), "l"(gptr) : "memory");
}
#define CP_COMMIT() asm volatile("cp.async.commit_group;" ::: "memory")
#define CP_WAIT(n)  asm volatile("cp.async.wait_group %0;" :: "n"(n) : "memory")

// ---------------------------------------------------------------------------
// K0: fused bias+mask table: g_bm[w][h][n][m] (m padded to 56 with -1e30)
// ---------------------------------------------------------------------------
__global__ void bm_kernel(const float* __restrict__ table,
                          const float* __restrict__ mask,
                          const int* __restrict__ rel_index)
{
    int i = blockIdx.x * blockDim.x + threadIdx.x;
    if (i >= 64 * NHEAD * SEQ * 56) return;
    int m = i % 56; int t = i / 56;
    int n = t % SEQ; t /= SEQ;
    int h = t % NHEAD; int w = t / NHEAD;
    float v = -1e30f;
    if (m < SEQ)
        v = table[rel_index[n * SEQ + m] * NHEAD + h]
          + mask[((size_t)w * SEQ + n) * SEQ + m];
    g_bm[i] = v;
}

// ---------------------------------------------------------------------------
// tf32 HMMA GEMM: cp.async 2-stage ring, one barrier/k-tile, 3 CTAs/SM.
//   Tile 128x96, BK=32, 256 thr = 8 warps (4M x 2N), warp tile 32x48.
//   2-stage: copy(kt+1) issued before compute(kt) -> one k-tile of LDG cover.
//   GRID: blockIdx.x = N-tile (fast) so A-tile sharers are co-resident (L2).
// ---------------------------------------------------------------------------
#define ABUF 4608u             // 128*36 floats
#define BBUF 3456u             // 96*36 floats
#define STAGE (ABUF + BBUF)
#define GEMM_SMEM_FLOATS (2u*STAGE)    // 16128 floats = 64512 B

template<bool PHASE1>
__global__ void __launch_bounds__(256, 3)
gemm_mma(const float* __restrict__ Ain, const float* __restrict__ W,
         const float* __restrict__ bias, float* __restrict__ Oin,
         int Ncols, float qscale)
{
    extern __shared__ float sm[];
    __shared__ float bias_s[96];

    const float* A = PHASE1 ? Ain : g_attn;
    float*       O = PHASE1 ? g_qkv : Oin;

    const int tid  = threadIdx.x;
    const int wid  = tid >> 5;
    const int lane = tid & 31;
    const int gid  = lane >> 2;
    const int tig  = lane & 3;
    const size_t m0 = (size_t)blockIdx.y * 128;   // M-tile: slow-varying
    const int    n0 = blockIdx.x * 96;            // N-tile: fast-varying
    const int    wm = (wid >> 1) * 32;
    const int    wn = (wid & 1) * 48;

    if (tid < 24) ((float4*)bias_s)[tid] = ((const float4*)(bias + n0))[tid];

    const int ra = tid >> 3;
    const int qa = tid & 7;
    const uint32_t smem_u32 = (uint32_t)__cvta_generic_to_shared(sm);

    auto cp_stage = [&](int kt, int buf) {
        const int k0 = kt * 32;
        const uint32_t sbase = smem_u32 + (uint32_t)(buf * STAGE) * 4u;
        #pragma unroll
        for (int i = 0; i < 4; ++i) {
            int r = ra + i * 32;
            cp16(sbase + (uint32_t)(r * 36 + qa * 4) * 4u,
                 A + (m0 + r) * (size_t)KD + k0 + qa * 4);
        }
        const uint32_t bbase = sbase + ABUF * 4u;
        #pragma unroll
        for (int i = 0; i < 3; ++i) {
            int r = ra + i * 32;
            cp16(bbase + (uint32_t)(r * 36 + qa * 4) * 4u,
                 W + (size_t)(n0 + r) * KD + k0 + qa * 4);
        }
        CP_COMMIT();
    };

    float acc[2][6][4] = {};

    // prologue: stage 0 in flight; wait, sync
    cp_stage(0, 0);
    CP_WAIT(0);
    __syncthreads();

    #pragma unroll 1
    for (int kt = 0; kt < 6; ++kt) {
        const int buf = kt & 1;
        if (kt < 5) cp_stage(kt + 1, buf ^ 1);   // other buffer, freed last iter

        const float* As = sm + buf * STAGE;
        const float* Bs = As + ABUF;

        #pragma unroll
        for (int kk = 0; kk < 32; kk += 8) {
            uint32_t afr[2][4], bfr[6][2];
            #pragma unroll
            for (int mi = 0; mi < 2; ++mi) {
                int r = wm + mi * 16 + gid;
                afr[mi][0] = f2tf32(As[r * 36 + kk + tig]);
                afr[mi][1] = f2tf32(As[(r + 8) * 36 + kk + tig]);
                afr[mi][2] = f2tf32(As[r * 36 + kk + 4 + tig]);
                afr[mi][3] = f2tf32(As[(r + 8) * 36 + kk + 4 + tig]);
            }
            #pragma unroll
            for (int ni = 0; ni < 6; ++ni) {
                int r = wn + ni * 8 + gid;
                bfr[ni][0] = f2tf32(Bs[r * 36 + kk + tig]);
                bfr[ni][1] = f2tf32(Bs[r * 36 + kk + 4 + tig]);
            }
            #pragma unroll
            for (int mi = 0; mi < 2; ++mi)
                #pragma unroll
                for (int ni = 0; ni < 6; ++ni)
                    mma_tf32(acc[mi][ni], afr[mi], bfr[ni]);
        }

        if (kt < 5) CP_WAIT(0);      // copy of kt+1 complete
        __syncthreads();
    }

    // ---- epilogue: stage to SMEM (stride 100), then coalesced STG ----
    float* stage = sm;               // 12800 floats <= 16128
    #pragma unroll
    for (int mi = 0; mi < 2; ++mi) {
        int row0 = wm + mi * 16 + gid;
        #pragma unroll
        for (int ni = 0; ni < 6; ++ni) {
            int col0 = wn + ni * 8 + 2 * tig;
            *(float2*)(stage + row0 * 100 + col0)       = make_float2(acc[mi][ni][0], acc[mi][ni][1]);
            *(float2*)(stage + (row0 + 8) * 100 + col0) = make_float2(acc[mi][ni][2], acc[mi][ni][3]);
        }
    }
    __syncthreads();

    const bool doscale = PHASE1 && (n0 < CDIM);
    #pragma unroll
    for (int i = 0; i < 12; ++i) {
        int idx = tid + i * 256;
        int row = idx / 24, c4 = idx - row * 24;
        float4 v  = *(float4*)(stage + row * 100 + c4 * 4);
        float4 bv = *(float4*)(bias_s + c4 * 4);
        float4 o;
        o.x = v.x + bv.x; o.y = v.y + bv.y; o.z = v.z + bv.z; o.w = v.w + bv.w;
        if (doscale) { o.x *= qscale; o.y *= qscale; o.z *= qscale; o.w *= qscale; }
        *(float4*)(O + (m0 + row) * (size_t)Ncols + n0 + c4 * 4) = o;
    }
}

// ---------------------------------------------------------------------------
// K2: tensor-core attention, plain single-pass tf32 (R10, unchanged).
// ---------------------------------------------------------------------------
#define QSTR 36
#define KSTR 36
#define VSTR 40
#define ATTN_SMEM_FLOATS (49*QSTR + 56*KSTR + 56*VSTR)   // 6020 -> 24080 B

__global__ void __launch_bounds__(128)
attn_mma()
{
    extern __shared__ float s[];
    float* qs = s;
    float* ks = qs + 49 * QSTR;
    float* vs = ks + 56 * KSTR;

    const int b = blockIdx.x;
    const int h = blockIdx.y;
    const int tid = threadIdx.x;
    const float* base = g_qkv + (size_t)b * SEQ * QKV_COLS;

    for (int i = tid; i < 49 * 8; i += 128) {
        int n = i >> 3, c = (i & 7) * 4;
        float4 v = *(const float4*)(base + n * QKV_COLS + h * HDIM + c);
        uint4 t = make_uint4(f2tf32(v.x), f2tf32(v.y), f2tf32(v.z), f2tf32(v.w));
        *(uint4*)(qs + n * QSTR + c) = t;
    }
    for (int i = tid; i < 56 * 8; i += 128) {
        int n = i >> 3, c = (i & 7) * 4;
        float4 kv = make_float4(0.f, 0.f, 0.f, 0.f), vv = kv;
        if (n < SEQ) {
            const float* src = base + n * QKV_COLS + CDIM + h * HDIM + c;
            kv = *(const float4*)src;
            vv = *(const float4*)(src + CDIM);
        }
        *(uint4*)(ks + n * KSTR + c) =
            make_uint4(f2tf32(kv.x), f2tf32(kv.y), f2tf32(kv.z), f2tf32(kv.w));
        *(uint4*)(vs + n * VSTR + c) =
            make_uint4(f2tf32(vv.x), f2tf32(vv.y), f2tf32(vv.z), f2tf32(vv.w));
    }
    __syncthreads();

    const int lane = tid & 31, w = tid >> 5;
    const int gid = lane >> 2, tig = lane & 3;
    const int row0 = w * 16 + gid, row1 = row0 + 8;
    const int r0c = min(row0, 48), r1c = min(row1, 48);

    float c[7][4] = {};
    #pragma unroll
    for (int kk = 0; kk < 4; ++kk) {
        const int dk = kk * 8;
        float a0 = qs[r0c * QSTR + dk + tig];
        float a1 = qs[r1c * QSTR + dk + tig];
        float a2 = qs[r0c * QSTR + dk + tig + 4];
        float a3 = qs[r1c * QSTR + dk + tig + 4];
        #pragma unroll
        for (int nt = 0; nt < 7; ++nt) {
            int kr = nt * 8 + gid;
            mma_f(c[nt], a0, a1, a2, a3,
                  ks[kr * KSTR + dk + tig], ks[kr * KSTR + dk + tig + 4]);
        }
    }

    const float* bmp = g_bm + ((size_t)((b & 63) * NHEAD + h)) * (SEQ * 56);
    #pragma unroll
    for (int nt = 0; nt < 7; ++nt) {
        float2 bm0 = *(const float2*)(bmp + r0c * 56 + nt * 8 + 2 * tig);
        float2 bm1 = *(const float2*)(bmp + r1c * 56 + nt * 8 + 2 * tig);
        c[nt][0] += bm0.x; c[nt][1] += bm0.y;
        c[nt][2] += bm1.x; c[nt][3] += bm1.y;
    }

    float mx0 = -1e30f, mx1 = -1e30f;
    #pragma unroll
    for (int nt = 0; nt < 7; ++nt) {
        mx0 = fmaxf(mx0, fmaxf(c[nt][0], c[nt][1]));
        mx1 = fmaxf(mx1, fmaxf(c[nt][2], c[nt][3]));
    }
    mx0 = fmaxf(mx0, __shfl_xor_sync(0xffffffffu, mx0, 1));
    mx0 = fmaxf(mx0, __shfl_xor_sync(0xffffffffu, mx0, 2));
    mx1 = fmaxf(mx1, __shfl_xor_sync(0xffffffffu, mx1, 1));
    mx1 = fmaxf(mx1, __shfl_xor_sync(0xffffffffu, mx1, 2));

    float s0 = 0.f, s1 = 0.f;
    #pragma unroll
    for (int nt = 0; nt < 7; ++nt) {
        c[nt][0] = __expf(c[nt][0] - mx0); s0 += c[nt][0];
        c[nt][1] = __expf(c[nt][1] - mx0); s0 += c[nt][1];
        c[nt][2] = __expf(c[nt][2] - mx1); s1 += c[nt][2];
        c[nt][3] = __expf(c[nt][3] - mx1); s1 += c[nt][3];
    }
    s0 += __shfl_xor_sync(0xffffffffu, s0, 1);
    s0 += __shfl_xor_sync(0xffffffffu, s0, 2);
    s1 += __shfl_xor_sync(0xffffffffu, s1, 1);
    s1 += __shfl_xor_sync(0xffffffffu, s1, 2);
    const float inv0 = 1.0f / s0, inv1 = 1.0f / s1;

    float o[4][4] = {};
    const int sA = (lane & ~3) | (tig >> 1);
    const int sB = sA + 2;
    const bool odd = tig & 1;
    #pragma unroll
    for (int j = 0; j < 7; ++j) {
        float t00 = __shfl_sync(0xffffffffu, c[j][0], sA);
        float t01 = __shfl_sync(0xffffffffu, c[j][1], sA);
        float t20 = __shfl_sync(0xffffffffu, c[j][0], sB);
        float t21 = __shfl_sync(0xffffffffu, c[j][1], sB);
        float t10 = __shfl_sync(0xffffffffu, c[j][2], sA);
        float t11 = __shfl_sync(0xffffffffu, c[j][3], sA);
        float t30 = __shfl_sync(0xffffffffu, c[j][2], sB);
        float t31 = __shfl_sync(0xffffffffu, c[j][3], sB);
        float a0 = __uint_as_float(f2tf32(odd ? t01 : t00));
        float a1 = __uint_as_float(f2tf32(odd ? t11 : t10));
        float a2 = __uint_as_float(f2tf32(odd ? t21 : t20));
        float a3 = __uint_as_float(f2tf32(odd ? t31 : t30));
        const int vr0 = j * 8 + tig, vr1 = vr0 + 4;
        #pragma unroll
        for (int nd = 0; nd < 4; ++nd) {
            int col = nd * 8 + gid;
            mma_f(o[nd], a0, a1, a2, a3,
                  vs[vr0 * VSTR + col], vs[vr1 * VSTR + col]);
        }
    }

    float* ob = g_attn + (size_t)b * SEQ * CDIM + h * HDIM;
    if (row0 < SEQ) {
        #pragma unroll
        for (int nd = 0; nd < 4; ++nd)
            *(float2*)(ob + row0 * CDIM + nd * 8 + 2 * tig) =
                make_float2(o[nd][0] * inv0, o[nd][1] * inv0);
    }
    if (row1 < SEQ) {
        #pragma unroll
        for (int nd = 0; nd < 4; ++nd)
            *(float2*)(ob + row1 * CDIM + nd * 8 + 2 * tig) =
                make_float2(o[nd][2] * inv1, o[nd][3] * inv1);
    }
}

// ---------------------------------------------------------------------------
extern "C" void kernel_launch(void* const* d_in, const int* in_sizes, int n_in,
                              void* d_out, int out_size)
{
    const float* x     = (const float*)d_in[0];
    const float* mask  = (const float*)d_in[1];
    const float* table = (const float*)d_in[2];
    const float* qkvw  = (const float*)d_in[3];
    const float* qkvb  = (const float*)d_in[4];
    const float* projw = (const float*)d_in[5];
    const float* projb = (const float*)d_in[6];
    const int*   relix = (const int*)d_in[7];
    float* out = (float*)d_out;

    const float qscale = 0.17677669529663687f;  // 1/sqrt(32)
    const int gemm_smem = GEMM_SMEM_FLOATS * 4;
    const int attn_smem = ATTN_SMEM_FLOATS * 4;

    cudaFuncSetAttribute((void*)gemm_mma<true>,
                         cudaFuncAttributeMaxDynamicSharedMemorySize, gemm_smem);
    cudaFuncSetAttribute((void*)gemm_mma<false>,
                         cudaFuncAttributeMaxDynamicSharedMemorySize, gemm_smem);
    cudaFuncSetAttribute((void*)attn_mma,
                         cudaFuncAttributeMaxDynamicSharedMemorySize, attn_smem);

    bm_kernel<<<(64 * NHEAD * SEQ * 56 + 255) / 256, 256>>>(table, mask, relix);

    // QKV: M=200704, N=576. N-tile fast-varying -> A-tile sharers co-resident.
    gemm_mma<true><<<dim3(6, MROWS / 128), 256, gemm_smem>>>(
        x, qkvw, qkvb, nullptr, QKV_COLS, qscale);

    attn_mma<<<dim3(B_WIN, NHEAD), 128, attn_smem>>>();

    // Proj: M=200704, N=192. Same N-fast ordering.
    gemm_mma<false><<<dim3(2, MROWS / 128), 256, gemm_smem>>>(
        nullptr, projw, projb, out, CDIM, 1.0f);
}

// round 12
// speedup vs baseline: 1.0656x; 1.0656x over previous
#include <cuda_runtime.h>
#include <cstdint>

// ---------------- problem constants ----------------
#define B_WIN    4096
#define SEQ      49
#define CDIM     192
#define NHEAD    6
#define HDIM     32
#define KD       192
#define QKV_COLS 576
#define MROWS    200704       // B_WIN * SEQ

// ---------------- scratch (__device__ globals, allocation-free) -------------
__device__ float g_qkv [(size_t)B_WIN * SEQ * QKV_COLS];
__device__ float g_attn[(size_t)B_WIN * SEQ * CDIM];   // tf32-rounded values
__device__ float g_bm  [64 * NHEAD * SEQ * 56];        // fused bias+mask
__device__ float g_wqkv [QKV_COLS * KD];               // tf32(s*W) bit patterns
__device__ float g_bqkv [QKV_COLS];                    // s*bias
__device__ float g_wproj[CDIM * KD];                   // tf32(W)

__device__ __forceinline__ uint32_t f2tf32(float x) {
    uint32_t r; asm("cvt.rna.tf32.f32 %0, %1;" : "=r"(r) : "f"(x)); return r;
}

__device__ __forceinline__ void mma_u(float* d, uint32_t a0, uint32_t a1,
                                      uint32_t a2, uint32_t a3,
                                      uint32_t b0, uint32_t b1) {
    asm volatile(
        "mma.sync.aligned.m16n8k8.row.col.f32.tf32.tf32.f32 "
        "{%0,%1,%2,%3}, {%4,%5,%6,%7}, {%8,%9}, {%0,%1,%2,%3};"
        : "+f"(d[0]), "+f"(d[1]), "+f"(d[2]), "+f"(d[3])
        : "r"(a0), "r"(a1), "r"(a2), "r"(a3), "r"(b0), "r"(b1));
}
__device__ __forceinline__ void mma_f(float* d, float a0, float a1, float a2, float a3,
                                      float b0, float b1) {
    mma_u(d, __float_as_uint(a0), __float_as_uint(a1),
          __float_as_uint(a2), __float_as_uint(a3),
          __float_as_uint(b0), __float_as_uint(b1));
}

__device__ __forceinline__ void cp16(uint32_t smem_addr, const void* gptr) {
    asm volatile("cp.async.cg.shared.global [%0], [%1], 16;"
                 :: "r"(smem_addr), "l"(gptr) : "memory");
}
#define CP_COMMIT() asm volatile("cp.async.commit_group;" ::: "memory")
#define CP_WAIT(n)  asm volatile("cp.async.wait_group %0;" :: "n"(n) : "memory")

// ---------------------------------------------------------------------------
// K0a: fused bias+mask table: g_bm[w][h][n][m] (m padded to 56 with -1e30)
// ---------------------------------------------------------------------------
__global__ void bm_kernel(const float* __restrict__ table,
                          const float* __restrict__ mask,
                          const int* __restrict__ rel_index)
{
    int i = blockIdx.x * blockDim.x + threadIdx.x;
    if (i >= 64 * NHEAD * SEQ * 56) return;
    int m = i % 56; int t = i / 56;
    int n = t % SEQ; t /= SEQ;
    int h = t % NHEAD; int w = t / NHEAD;
    float v = -1e30f;
    if (m < SEQ)
        v = table[rel_index[n * SEQ + m] * NHEAD + h]
          + mask[((size_t)w * SEQ + n) * SEQ + m];
    g_bm[i] = v;
}

// ---------------------------------------------------------------------------
// K0b: weight prep — pre-round weights to tf32 (q rows pre-scaled), scale bias.
// ---------------------------------------------------------------------------
__global__ void wprep_kernel(const float* __restrict__ qkvw,
                             const float* __restrict__ qkvb,
                             const float* __restrict__ projw)
{
    const float qs = 0.17677669529663687f;   // 1/sqrt(32)
    int i = blockIdx.x * blockDim.x + threadIdx.x;
    if (i < QKV_COLS * KD) {
        float w = qkvw[i];
        if (i < CDIM * KD) w *= qs;          // q rows are the first 192
        g_wqkv[i] = __uint_as_float(f2tf32(w));
    }
    if (i < CDIM * KD)
        g_wproj[i] = __uint_as_float(f2tf32(projw[i]));
    if (i < QKV_COLS) {
        float b = qkvb[i];
        if (i < CDIM) b *= qs;
        g_bqkv[i] = b;
    }
}

// ---------------------------------------------------------------------------
// tf32 HMMA GEMM: cp.async 3-stage ring, one barrier/k-tile, 2 CTAs/SM (R10).
//   B side pre-rounded tf32 -> raw LDS, no cvt. A side: cvt only for PHASE1
//   (x is fp32); proj A (g_attn) is pre-rounded -> raw LDS.
//   GRID: blockIdx.x = N-tile (fast) so A-tile sharers are co-resident (L2).
// ---------------------------------------------------------------------------
#define ABUF 4608u             // 128*36 floats
#define BBUF 3456u             // 96*36 floats
#define STAGE (ABUF + BBUF)
#define GEMM_SMEM_FLOATS (3u*STAGE)    // 24192 floats = 96768 B

template<bool PHASE1>
__global__ void __launch_bounds__(256, 2)
gemm_mma(const float* __restrict__ Ain, const float* __restrict__ bias_in,
         float* __restrict__ Oin, int Ncols)
{
    extern __shared__ float sm[];
    __shared__ float bias_s[96];

    const float* A = PHASE1 ? Ain : g_attn;
    const float* W = PHASE1 ? g_wqkv : g_wproj;
    const float* bias = PHASE1 ? g_bqkv : bias_in;
    float*       O = PHASE1 ? g_qkv : Oin;

    const int tid  = threadIdx.x;
    const int wid  = tid >> 5;
    const int lane = tid & 31;
    const int gid  = lane >> 2;
    const int tig  = lane & 3;
    const size_t m0 = (size_t)blockIdx.y * 128;   // M-tile: slow-varying
    const int    n0 = blockIdx.x * 96;            // N-tile: fast-varying
    const int    wm = (wid >> 1) * 32;
    const int    wn = (wid & 1) * 48;

    if (tid < 24) ((float4*)bias_s)[tid] = ((const float4*)(bias + n0))[tid];

    const int ra = tid >> 3;
    const int qa = tid & 7;
    const uint32_t smem_u32 = (uint32_t)__cvta_generic_to_shared(sm);

    auto cp_stage = [&](int kt, int buf) {
        const int k0 = kt * 32;
        const uint32_t sbase = smem_u32 + (uint32_t)(buf * STAGE) * 4u;
        #pragma unroll
        for (int i = 0; i < 4; ++i) {
            int r = ra + i * 32;
            cp16(sbase + (uint32_t)(r * 36 + qa * 4) * 4u,
                 A + (m0 + r) * (size_t)KD + k0 + qa * 4);
        }
        const uint32_t bbase = sbase + ABUF * 4u;
        #pragma unroll
        for (int i = 0; i < 3; ++i) {
            int r = ra + i * 32;
            cp16(bbase + (uint32_t)(r * 36 + qa * 4) * 4u,
                 W + (size_t)(n0 + r) * KD + k0 + qa * 4);
        }
        CP_COMMIT();
    };

    float acc[2][6][4] = {};

    cp_stage(0, 0);
    cp_stage(1, 1);
    CP_WAIT(1);
    __syncthreads();

    #pragma unroll 1
    for (int kt = 0; kt < 6; ++kt) {
        const int buf = kt % 3;
        const float* As = sm + buf * STAGE;
        const float* Bs = As + ABUF;

        #pragma unroll
        for (int kk = 0; kk < 32; kk += 8) {
            uint32_t afr[2][4], bfr[6][2];
            #pragma unroll
            for (int mi = 0; mi < 2; ++mi) {
                int r = wm + mi * 16 + gid;
                if (PHASE1) {
                    afr[mi][0] = f2tf32(As[r * 36 + kk + tig]);
                    afr[mi][1] = f2tf32(As[(r + 8) * 36 + kk + tig]);
                    afr[mi][2] = f2tf32(As[r * 36 + kk + 4 + tig]);
                    afr[mi][3] = f2tf32(As[(r + 8) * 36 + kk + 4 + tig]);
                } else {
                    afr[mi][0] = __float_as_uint(As[r * 36 + kk + tig]);
                    afr[mi][1] = __float_as_uint(As[(r + 8) * 36 + kk + tig]);
                    afr[mi][2] = __float_as_uint(As[r * 36 + kk + 4 + tig]);
                    afr[mi][3] = __float_as_uint(As[(r + 8) * 36 + kk + 4 + tig]);
                }
            }
            #pragma unroll
            for (int ni = 0; ni < 6; ++ni) {
                int r = wn + ni * 8 + gid;
                bfr[ni][0] = __float_as_uint(Bs[r * 36 + kk + tig]);
                bfr[ni][1] = __float_as_uint(Bs[r * 36 + kk + 4 + tig]);
            }
            #pragma unroll
            for (int mi = 0; mi < 2; ++mi)
                #pragma unroll
                for (int ni = 0; ni < 6; ++ni)
                    mma_u(acc[mi][ni], afr[mi][0], afr[mi][1], afr[mi][2], afr[mi][3],
                          bfr[ni][0], bfr[ni][1]);
        }

        if (kt < 4) {
            cp_stage(kt + 2, (kt + 2) % 3);
            CP_WAIT(1);
        } else if (kt == 4) {
            CP_WAIT(0);
        }
        __syncthreads();
    }

    // ---- epilogue: stage to SMEM (stride 100), then coalesced STG ----
    float* stage = sm;
    #pragma unroll
    for (int mi = 0; mi < 2; ++mi) {
        int row0 = wm + mi * 16 + gid;
        #pragma unroll
        for (int ni = 0; ni < 6; ++ni) {
            int col0 = wn + ni * 8 + 2 * tig;
            *(float2*)(stage + row0 * 100 + col0)       = make_float2(acc[mi][ni][0], acc[mi][ni][1]);
            *(float2*)(stage + (row0 + 8) * 100 + col0) = make_float2(acc[mi][ni][2], acc[mi][ni][3]);
        }
    }
    __syncthreads();

    #pragma unroll
    for (int i = 0; i < 12; ++i) {
        int idx = tid + i * 256;
        int row = idx / 24, c4 = idx - row * 24;
        float4 v  = *(float4*)(stage + row * 100 + c4 * 4);
        float4 bv = *(float4*)(bias_s + c4 * 4);
        float4 o;
        o.x = v.x + bv.x; o.y = v.y + bv.y; o.z = v.z + bv.z; o.w = v.w + bv.w;
        *(float4*)(O + (m0 + row) * (size_t)Ncols + n0 + c4 * 4) = o;
    }
}

// ---------------------------------------------------------------------------
// K2: tensor-core attention, plain single-pass tf32 (R10), output written
// PRE-ROUNDED to tf32 so the proj GEMM needs no A-side cvt (bit-identical).
// ---------------------------------------------------------------------------
#define QSTR 36
#define KSTR 36
#define VSTR 40
#define ATTN_SMEM_FLOATS (49*QSTR + 56*KSTR + 56*VSTR)   // 6020 -> 24080 B

__global__ void __launch_bounds__(128)
attn_mma()
{
    extern __shared__ float s[];
    float* qs = s;
    float* ks = qs + 49 * QSTR;
    float* vs = ks + 56 * KSTR;

    const int b = blockIdx.x;
    const int h = blockIdx.y;
    const int tid = threadIdx.x;
    const float* base = g_qkv + (size_t)b * SEQ * QKV_COLS;

    for (int i = tid; i < 49 * 8; i += 128) {
        int n = i >> 3, c = (i & 7) * 4;
        float4 v = *(const float4*)(base + n * QKV_COLS + h * HDIM + c);
        uint4 t = make_uint4(f2tf32(v.x), f2tf32(v.y), f2tf32(v.z), f2tf32(v.w));
        *(uint4*)(qs + n * QSTR + c) = t;
    }
    for (int i = tid; i < 56 * 8; i += 128) {
        int n = i >> 3, c = (i & 7) * 4;
        float4 kv = make_float4(0.f, 0.f, 0.f, 0.f), vv = kv;
        if (n < SEQ) {
            const float* src = base + n * QKV_COLS + CDIM + h * HDIM + c;
            kv = *(const float4*)src;
            vv = *(const float4*)(src + CDIM);
        }
        *(uint4*)(ks + n * KSTR + c) =
            make_uint4(f2tf32(kv.x), f2tf32(kv.y), f2tf32(kv.z), f2tf32(kv.w));
        *(uint4*)(vs + n * VSTR + c) =
            make_uint4(f2tf32(vv.x), f2tf32(vv.y), f2tf32(vv.z), f2tf32(vv.w));
    }
    __syncthreads();

    const int lane = tid & 31, w = tid >> 5;
    const int gid = lane >> 2, tig = lane & 3;
    const int row0 = w * 16 + gid, row1 = row0 + 8;
    const int r0c = min(row0, 48), r1c = min(row1, 48);

    float c[7][4] = {};
    #pragma unroll
    for (int kk = 0; kk < 4; ++kk) {
        const int dk = kk * 8;
        float a0 = qs[r0c * QSTR + dk + tig];
        float a1 = qs[r1c * QSTR + dk + tig];
        float a2 = qs[r0c * QSTR + dk + tig + 4];
        float a3 = qs[r1c * QSTR + dk + tig + 4];
        #pragma unroll
        for (int nt = 0; nt < 7; ++nt) {
            int kr = nt * 8 + gid;
            mma_f(c[nt], a0, a1, a2, a3,
                  ks[kr * KSTR + dk + tig], ks[kr * KSTR + dk + tig + 4]);
        }
    }

    const float* bmp = g_bm + ((size_t)((b & 63) * NHEAD + h)) * (SEQ * 56);
    #pragma unroll
    for (int nt = 0; nt < 7; ++nt) {
        float2 bm0 = *(const float2*)(bmp + r0c * 56 + nt * 8 + 2 * tig);
        float2 bm1 = *(const float2*)(bmp + r1c * 56 + nt * 8 + 2 * tig);
        c[nt][0] += bm0.x; c[nt][1] += bm0.y;
        c[nt][2] += bm1.x; c[nt][3] += bm1.y;
    }

    float mx0 = -1e30f, mx1 = -1e30f;
    #pragma unroll
    for (int nt = 0; nt < 7; ++nt) {
        mx0 = fmaxf(mx0, fmaxf(c[nt][0], c[nt][1]));
        mx1 = fmaxf(mx1, fmaxf(c[nt][2], c[nt][3]));
    }
    mx0 = fmaxf(mx0, __shfl_xor_sync(0xffffffffu, mx0, 1));
    mx0 = fmaxf(mx0, __shfl_xor_sync(0xffffffffu, mx0, 2));
    mx1 = fmaxf(mx1, __shfl_xor_sync(0xffffffffu, mx1, 1));
    mx1 = fmaxf(mx1, __shfl_xor_sync(0xffffffffu, mx1, 2));

    float s0 = 0.f, s1 = 0.f;
    #pragma unroll
    for (int nt = 0; nt < 7; ++nt) {
        c[nt][0] = __expf(c[nt][0] - mx0); s0 += c[nt][0];
        c[nt][1] = __expf(c[nt][1] - mx0); s0 += c[nt][1];
        c[nt][2] = __expf(c[nt][2] - mx1); s1 += c[nt][2];
        c[nt][3] = __expf(c[nt][3] - mx1); s1 += c[nt][3];
    }
    s0 += __shfl_xor_sync(0xffffffffu, s0, 1);
    s0 += __shfl_xor_sync(0xffffffffu, s0, 2);
    s1 += __shfl_xor_sync(0xffffffffu, s1, 1);
    s1 += __shfl_xor_sync(0xffffffffu, s1, 2);
    const float inv0 = 1.0f / s0, inv1 = 1.0f / s1;

    float o[4][4] = {};
    const int sA = (lane & ~3) | (tig >> 1);
    const int sB = sA + 2;
    const bool odd = tig & 1;
    #pragma unroll
    for (int j = 0; j < 7; ++j) {
        float t00 = __shfl_sync(0xffffffffu, c[j][0], sA);
        float t01 = __shfl_sync(0xffffffffu, c[j][1], sA);
        float t20 = __shfl_sync(0xffffffffu, c[j][0], sB);
        float t21 = __shfl_sync(0xffffffffu, c[j][1], sB);
        float t10 = __shfl_sync(0xffffffffu, c[j][2], sA);
        float t11 = __shfl_sync(0xffffffffu, c[j][3], sA);
        float t30 = __shfl_sync(0xffffffffu, c[j][2], sB);
        float t31 = __shfl_sync(0xffffffffu, c[j][3], sB);
        float a0 = __uint_as_float(f2tf32(odd ? t01 : t00));
        float a1 = __uint_as_float(f2tf32(odd ? t11 : t10));
        float a2 = __uint_as_float(f2tf32(odd ? t21 : t20));
        float a3 = __uint_as_float(f2tf32(odd ? t31 : t30));
        const int vr0 = j * 8 + tig, vr1 = vr0 + 4;
        #pragma unroll
        for (int nd = 0; nd < 4; ++nd) {
            int col = nd * 8 + gid;
            mma_f(o[nd], a0, a1, a2, a3,
                  vs[vr0 * VSTR + col], vs[vr1 * VSTR + col]);
        }
    }

    // write pre-rounded tf32 (same values the proj kernel would have produced)
    float* ob = g_attn + (size_t)b * SEQ * CDIM + h * HDIM;
    if (row0 < SEQ) {
        #pragma unroll
        for (int nd = 0; nd < 4; ++nd)
            *(float2*)(ob + row0 * CDIM + nd * 8 + 2 * tig) =
                make_float2(__uint_as_float(f2tf32(o[nd][0] * inv0)),
                            __uint_as_float(f2tf32(o[nd][1] * inv0)));
    }
    if (row1 < SEQ) {
        #pragma unroll
        for (int nd = 0; nd < 4; ++nd)
            *(float2*)(ob + row1 * CDIM + nd * 8 + 2 * tig) =
                make_float2(__uint_as_float(f2tf32(o[nd][2] * inv1)),
                            __uint_as_float(f2tf32(o[nd][3] * inv1)));
    }
}

// ---------------------------------------------------------------------------
extern "C" void kernel_launch(void* const* d_in, const int* in_sizes, int n_in,
                              void* d_out, int out_size)
{
    const float* x     = (const float*)d_in[0];
    const float* mask  = (const float*)d_in[1];
    const float* table = (const float*)d_in[2];
    const float* qkvw  = (const float*)d_in[3];
    const float* qkvb  = (const float*)d_in[4];
    const float* projw = (const float*)d_in[5];
    const float* projb = (const float*)d_in[6];
    const int*   relix = (const int*)d_in[7];
    float* out = (float*)d_out;

    const int gemm_smem = GEMM_SMEM_FLOATS * 4;
    const int attn_smem = ATTN_SMEM_FLOATS * 4;

    cudaFuncSetAttribute((void*)gemm_mma<true>,
                         cudaFuncAttributeMaxDynamicSharedMemorySize, gemm_smem);
    cudaFuncSetAttribute((void*)gemm_mma<false>,
                         cudaFuncAttributeMaxDynamicSharedMemorySize, gemm_smem);
    cudaFuncSetAttribute((void*)attn_mma,
                         cudaFuncAttributeMaxDynamicSharedMemorySize, attn_smem);

    bm_kernel<<<(64 * NHEAD * SEQ * 56 + 255) / 256, 256>>>(table, mask, relix);
    wprep_kernel<<<(QKV_COLS * KD + 255) / 256, 256>>>(qkvw, qkvb, projw);

    // QKV: M=200704, N=576. N-tile fast-varying -> A-tile sharers co-resident.
    gemm_mma<true><<<dim3(6, MROWS / 128), 256, gemm_smem>>>(
        x, nullptr, nullptr, QKV_COLS);

    attn_mma<<<dim3(B_WIN, NHEAD), 128, attn_smem>>>();

    // Proj: M=200704, N=192. Same N-fast ordering.
    gemm_mma<false><<<dim3(2, MROWS / 128), 256, gemm_smem>>>(
        nullptr, projb, out, CDIM);
}

// round 13
// speedup vs baseline: 1.1246x; 1.0553x over previous
#include <cuda_runtime.h>
#include <cstdint>

// ---------------- problem constants ----------------
#define B_WIN    4096
#define SEQ      49
#define CDIM     192
#define NHEAD    6
#define HDIM     32
#define KD       192
#define QKV_COLS 576
#define MROWS    200704       // B_WIN * SEQ

// ---------------- scratch (__device__ globals, allocation-free) -------------
__device__ float g_qkv [(size_t)B_WIN * SEQ * QKV_COLS];
__device__ float g_attn[(size_t)B_WIN * SEQ * CDIM];   // tf32-rounded values
__device__ float g_bm  [64 * NHEAD * SEQ * 56];        // fused bias+mask
__device__ float g_wqkv [QKV_COLS * KD];               // tf32(s*W) bit patterns
__device__ float g_bqkv [QKV_COLS];                    // s*bias
__device__ float g_wproj[CDIM * KD];                   // tf32(W)

__device__ __forceinline__ uint32_t f2tf32(float x) {
    uint32_t r; asm("cvt.rna.tf32.f32 %0, %1;" : "=r"(r) : "f"(x)); return r;
}

__device__ __forceinline__ void mma_u(float* d, uint32_t a0, uint32_t a1,
                                      uint32_t a2, uint32_t a3,
                                      uint32_t b0, uint32_t b1) {
    asm volatile(
        "mma.sync.aligned.m16n8k8.row.col.f32.tf32.tf32.f32 "
        "{%0,%1,%2,%3}, {%4,%5,%6,%7}, {%8,%9}, {%0,%1,%2,%3};"
        : "+f"(d[0]), "+f"(d[1]), "+f"(d[2]), "+f"(d[3])
        : "r"(a0), "r"(a1), "r"(a2), "r"(a3), "r"(b0), "r"(b1));
}
__device__ __forceinline__ void mma_f(float* d, float a0, float a1, float a2, float a3,
                                      float b0, float b1) {
    mma_u(d, __float_as_uint(a0), __float_as_uint(a1),
          __float_as_uint(a2), __float_as_uint(a3),
          __float_as_uint(b0), __float_as_uint(b1));
}

__device__ __forceinline__ void cp16(uint32_t smem_addr, const void* gptr) {
    asm volatile("cp.async.cg.shared.global [%0], [%1], 16;"
                 :: "r"(smem_addr), "l"(gptr) : "memory");
}
#define CP_COMMIT() asm volatile("cp.async.commit_group;" ::: "memory")
#define CP_WAIT(n)  asm volatile("cp.async.wait_group %0;" :: "n"(n) : "memory")

// ---------------------------------------------------------------------------
// K0a: fused bias+mask table: g_bm[w][h][n][m] (m padded to 56 with -1e30)
// ---------------------------------------------------------------------------
__global__ void bm_kernel(const float* __restrict__ table,
                          const float* __restrict__ mask,
                          const int* __restrict__ rel_index)
{
    int i = blockIdx.x * blockDim.x + threadIdx.x;
    if (i >= 64 * NHEAD * SEQ * 56) return;
    int m = i % 56; int t = i / 56;
    int n = t % SEQ; t /= SEQ;
    int h = t % NHEAD; int w = t / NHEAD;
    float v = -1e30f;
    if (m < SEQ)
        v = table[rel_index[n * SEQ + m] * NHEAD + h]
          + mask[((size_t)w * SEQ + n) * SEQ + m];
    g_bm[i] = v;
}

// ---------------------------------------------------------------------------
// K0b: weight prep — pre-round weights to tf32 (q rows pre-scaled), scale bias.
// ---------------------------------------------------------------------------
__global__ void wprep_kernel(const float* __restrict__ qkvw,
                             const float* __restrict__ qkvb,
                             const float* __restrict__ projw)
{
    const float qs = 0.17677669529663687f;   // 1/sqrt(32)
    int i = blockIdx.x * blockDim.x + threadIdx.x;
    if (i < QKV_COLS * KD) {
        float w = qkvw[i];
        if (i < CDIM * KD) w *= qs;          // q rows are the first 192
        g_wqkv[i] = __uint_as_float(f2tf32(w));
    }
    if (i < CDIM * KD)
        g_wproj[i] = __uint_as_float(f2tf32(projw[i]));
    if (i < QKV_COLS) {
        float b = qkvb[i];
        if (i < CDIM) b *= qs;
        g_bqkv[i] = b;
    }
}

// ---------------------------------------------------------------------------
// tf32 HMMA GEMM v2: 128 threads (4 warps), warp tile 64x48 (2M x 2N),
//   CTA tile 128x96, 2-stage cp.async ring, 3 CTAs/SM.
//   28 LDS per 24 MMAs (was 20/12). B pre-rounded tf32; A cvt only in PHASE1.
//   GRID: blockIdx.x = N-tile (fast) so A-tile sharers are co-resident (L2).
// ---------------------------------------------------------------------------
#define ABUF 4608u             // 128*36 floats
#define BBUF 3456u             // 96*36 floats
#define STAGE (ABUF + BBUF)
#define GEMM_SMEM_FLOATS (2u*STAGE)    // 16128 floats = 64512 B

template<bool PHASE1>
__global__ void __launch_bounds__(128, 3)
gemm_mma(const float* __restrict__ Ain, const float* __restrict__ bias_in,
         float* __restrict__ Oin, int Ncols)
{
    extern __shared__ float sm[];
    __shared__ float bias_s[96];

    const float* A = PHASE1 ? Ain : g_attn;
    const float* W = PHASE1 ? g_wqkv : g_wproj;
    const float* bias = PHASE1 ? g_bqkv : bias_in;
    float*       O = PHASE1 ? g_qkv : Oin;

    const int tid  = threadIdx.x;
    const int wid  = tid >> 5;
    const int lane = tid & 31;
    const int gid  = lane >> 2;
    const int tig  = lane & 3;
    const size_t m0 = (size_t)blockIdx.y * 128;   // M-tile: slow-varying
    const int    n0 = blockIdx.x * 96;            // N-tile: fast-varying
    const int    wm = (wid >> 1) * 64;            // 2 M groups of 64
    const int    wn = (wid & 1) * 48;             // 2 N groups of 48

    if (tid < 24) ((float4*)bias_s)[tid] = ((const float4*)(bias + n0))[tid];

    const int ra = tid >> 3;          // 0..15
    const int qa = tid & 7;
    const uint32_t smem_u32 = (uint32_t)__cvta_generic_to_shared(sm);

    auto cp_stage = [&](int kt, int buf) {
        const int k0 = kt * 32;
        const uint32_t sbase = smem_u32 + (uint32_t)(buf * STAGE) * 4u;
        #pragma unroll
        for (int i = 0; i < 8; ++i) {             // A: 128 rows x 8 float4
            int r = ra + i * 16;
            cp16(sbase + (uint32_t)(r * 36 + qa * 4) * 4u,
                 A + (m0 + r) * (size_t)KD + k0 + qa * 4);
        }
        const uint32_t bbase = sbase + ABUF * 4u;
        #pragma unroll
        for (int i = 0; i < 6; ++i) {             // B: 96 rows x 8 float4
            int r = ra + i * 16;
            cp16(bbase + (uint32_t)(r * 36 + qa * 4) * 4u,
                 W + (size_t)(n0 + r) * KD + k0 + qa * 4);
        }
        CP_COMMIT();
    };

    float acc[4][6][4] = {};

    cp_stage(0, 0);
    CP_WAIT(0);
    __syncthreads();

    #pragma unroll 1
    for (int kt = 0; kt < 6; ++kt) {
        const int buf = kt & 1;
        if (kt < 5) cp_stage(kt + 1, buf ^ 1);

        const float* As = sm + buf * STAGE;
        const float* Bs = As + ABUF;

        #pragma unroll
        for (int kk = 0; kk < 32; kk += 8) {
            uint32_t afr[4][4], bfr[6][2];
            #pragma unroll
            for (int mi = 0; mi < 4; ++mi) {
                int r = wm + mi * 16 + gid;
                if (PHASE1) {
                    afr[mi][0] = f2tf32(As[r * 36 + kk + tig]);
                    afr[mi][1] = f2tf32(As[(r + 8) * 36 + kk + tig]);
                    afr[mi][2] = f2tf32(As[r * 36 + kk + 4 + tig]);
                    afr[mi][3] = f2tf32(As[(r + 8) * 36 + kk + 4 + tig]);
                } else {
                    afr[mi][0] = __float_as_uint(As[r * 36 + kk + tig]);
                    afr[mi][1] = __float_as_uint(As[(r + 8) * 36 + kk + tig]);
                    afr[mi][2] = __float_as_uint(As[r * 36 + kk + 4 + tig]);
                    afr[mi][3] = __float_as_uint(As[(r + 8) * 36 + kk + 4 + tig]);
                }
            }
            #pragma unroll
            for (int ni = 0; ni < 6; ++ni) {
                int r = wn + ni * 8 + gid;
                bfr[ni][0] = __float_as_uint(Bs[r * 36 + kk + tig]);
                bfr[ni][1] = __float_as_uint(Bs[r * 36 + kk + 4 + tig]);
            }
            #pragma unroll
            for (int mi = 0; mi < 4; ++mi)
                #pragma unroll
                for (int ni = 0; ni < 6; ++ni)
                    mma_u(acc[mi][ni], afr[mi][0], afr[mi][1], afr[mi][2], afr[mi][3],
                          bfr[ni][0], bfr[ni][1]);
        }

        if (kt < 5) CP_WAIT(0);
        __syncthreads();
    }

    // ---- epilogue: stage to SMEM (stride 100), then coalesced STG ----
    float* stage = sm;               // 12800 floats <= 16128
    #pragma unroll
    for (int mi = 0; mi < 4; ++mi) {
        int row0 = wm + mi * 16 + gid;
        #pragma unroll
        for (int ni = 0; ni < 6; ++ni) {
            int col0 = wn + ni * 8 + 2 * tig;
            *(float2*)(stage + row0 * 100 + col0)       = make_float2(acc[mi][ni][0], acc[mi][ni][1]);
            *(float2*)(stage + (row0 + 8) * 100 + col0) = make_float2(acc[mi][ni][2], acc[mi][ni][3]);
        }
    }
    __syncthreads();

    #pragma unroll
    for (int i = 0; i < 24; ++i) {   // 128*96/4 = 3072 float4
        int idx = tid + i * 128;
        int row = idx / 24, c4 = idx - row * 24;
        float4 v  = *(float4*)(stage + row * 100 + c4 * 4);
        float4 bv = *(float4*)(bias_s + c4 * 4);
        float4 o;
        o.x = v.x + bv.x; o.y = v.y + bv.y; o.z = v.z + bv.z; o.w = v.w + bv.w;
        *(float4*)(O + (m0 + row) * (size_t)Ncols + n0 + c4 * 4) = o;
    }
}

// ---------------------------------------------------------------------------
// K2: tensor-core attention, plain single-pass tf32 (R12, unchanged).
// ---------------------------------------------------------------------------
#define QSTR 36
#define KSTR 36
#define VSTR 40
#define ATTN_SMEM_FLOATS (49*QSTR + 56*KSTR + 56*VSTR)   // 6020 -> 24080 B

__global__ void __launch_bounds__(128)
attn_mma()
{
    extern __shared__ float s[];
    float* qs = s;
    float* ks = qs + 49 * QSTR;
    float* vs = ks + 56 * KSTR;

    const int b = blockIdx.x;
    const int h = blockIdx.y;
    const int tid = threadIdx.x;
    const float* base = g_qkv + (size_t)b * SEQ * QKV_COLS;

    for (int i = tid; i < 49 * 8; i += 128) {
        int n = i >> 3, c = (i & 7) * 4;
        float4 v = *(const float4*)(base + n * QKV_COLS + h * HDIM + c);
        uint4 t = make_uint4(f2tf32(v.x), f2tf32(v.y), f2tf32(v.z), f2tf32(v.w));
        *(uint4*)(qs + n * QSTR + c) = t;
    }
    for (int i = tid; i < 56 * 8; i += 128) {
        int n = i >> 3, c = (i & 7) * 4;
        float4 kv = make_float4(0.f, 0.f, 0.f, 0.f), vv = kv;
        if (n < SEQ) {
            const float* src = base + n * QKV_COLS + CDIM + h * HDIM + c;
            kv = *(const float4*)src;
            vv = *(const float4*)(src + CDIM);
        }
        *(uint4*)(ks + n * KSTR + c) =
            make_uint4(f2tf32(kv.x), f2tf32(kv.y), f2tf32(kv.z), f2tf32(kv.w));
        *(uint4*)(vs + n * VSTR + c) =
            make_uint4(f2tf32(vv.x), f2tf32(vv.y), f2tf32(vv.z), f2tf32(vv.w));
    }
    __syncthreads();

    const int lane = tid & 31, w = tid >> 5;
    const int gid = lane >> 2, tig = lane & 3;
    const int row0 = w * 16 + gid, row1 = row0 + 8;
    const int r0c = min(row0, 48), r1c = min(row1, 48);

    float c[7][4] = {};
    #pragma unroll
    for (int kk = 0; kk < 4; ++kk) {
        const int dk = kk * 8;
        float a0 = qs[r0c * QSTR + dk + tig];
        float a1 = qs[r1c * QSTR + dk + tig];
        float a2 = qs[r0c * QSTR + dk + tig + 4];
        float a3 = qs[r1c * QSTR + dk + tig + 4];
        #pragma unroll
        for (int nt = 0; nt < 7; ++nt) {
            int kr = nt * 8 + gid;
            mma_f(c[nt], a0, a1, a2, a3,
                  ks[kr * KSTR + dk + tig], ks[kr * KSTR + dk + tig + 4]);
        }
    }

    const float* bmp = g_bm + ((size_t)((b & 63) * NHEAD + h)) * (SEQ * 56);
    #pragma unroll
    for (int nt = 0; nt < 7; ++nt) {
        float2 bm0 = *(const float2*)(bmp + r0c * 56 + nt * 8 + 2 * tig);
        float2 bm1 = *(const float2*)(bmp + r1c * 56 + nt * 8 + 2 * tig);
        c[nt][0] += bm0.x; c[nt][1] += bm0.y;
        c[nt][2] += bm1.x; c[nt][3] += bm1.y;
    }

    float mx0 = -1e30f, mx1 = -1e30f;
    #pragma unroll
    for (int nt = 0; nt < 7; ++nt) {
        mx0 = fmaxf(mx0, fmaxf(c[nt][0], c[nt][1]));
        mx1 = fmaxf(mx1, fmaxf(c[nt][2], c[nt][3]));
    }
    mx0 = fmaxf(mx0, __shfl_xor_sync(0xffffffffu, mx0, 1));
    mx0 = fmaxf(mx0, __shfl_xor_sync(0xffffffffu, mx0, 2));
    mx1 = fmaxf(mx1, __shfl_xor_sync(0xffffffffu, mx1, 1));
    mx1 = fmaxf(mx1, __shfl_xor_sync(0xffffffffu, mx1, 2));

    float s0 = 0.f, s1 = 0.f;
    #pragma unroll
    for (int nt = 0; nt < 7; ++nt) {
        c[nt][0] = __expf(c[nt][0] - mx0); s0 += c[nt][0];
        c[nt][1] = __expf(c[nt][1] - mx0); s0 += c[nt][1];
        c[nt][2] = __expf(c[nt][2] - mx1); s1 += c[nt][2];
        c[nt][3] = __expf(c[nt][3] - mx1); s1 += c[nt][3];
    }
    s0 += __shfl_xor_sync(0xffffffffu, s0, 1);
    s0 += __shfl_xor_sync(0xffffffffu, s0, 2);
    s1 += __shfl_xor_sync(0xffffffffu, s1, 1);
    s1 += __shfl_xor_sync(0xffffffffu, s1, 2);
    const float inv0 = 1.0f / s0, inv1 = 1.0f / s1;

    float o[4][4] = {};
    const int sA = (lane & ~3) | (tig >> 1);
    const int sB = sA + 2;
    const bool odd = tig & 1;
    #pragma unroll
    for (int j = 0; j < 7; ++j) {
        float t00 = __shfl_sync(0xffffffffu, c[j][0], sA);
        float t01 = __shfl_sync(0xffffffffu, c[j][1], sA);
        float t20 = __shfl_sync(0xffffffffu, c[j][0], sB);
        float t21 = __shfl_sync(0xffffffffu, c[j][1], sB);
        float t10 = __shfl_sync(0xffffffffu, c[j][2], sA);
        float t11 = __shfl_sync(0xffffffffu, c[j][3], sA);
        float t30 = __shfl_sync(0xffffffffu, c[j][2], sB);
        float t31 = __shfl_sync(0xffffffffu, c[j][3], sB);
        float a0 = __uint_as_float(f2tf32(odd ? t01 : t00));
        float a1 = __uint_as_float(f2tf32(odd ? t11 : t10));
        float a2 = __uint_as_float(f2tf32(odd ? t21 : t20));
        float a3 = __uint_as_float(f2tf32(odd ? t31 : t30));
        const int vr0 = j * 8 + tig, vr1 = vr0 + 4;
        #pragma unroll
        for (int nd = 0; nd < 4; ++nd) {
            int col = nd * 8 + gid;
            mma_f(o[nd], a0, a1, a2, a3,
                  vs[vr0 * VSTR + col], vs[vr1 * VSTR + col]);
        }
    }

    float* ob = g_attn + (size_t)b * SEQ * CDIM + h * HDIM;
    if (row0 < SEQ) {
        #pragma unroll
        for (int nd = 0; nd < 4; ++nd)
            *(float2*)(ob + row0 * CDIM + nd * 8 + 2 * tig) =
                make_float2(__uint_as_float(f2tf32(o[nd][0] * inv0)),
                            __uint_as_float(f2tf32(o[nd][1] * inv0)));
    }
    if (row1 < SEQ) {
        #pragma unroll
        for (int nd = 0; nd < 4; ++nd)
            *(float2*)(ob + row1 * CDIM + nd * 8 + 2 * tig) =
                make_float2(__uint_as_float(f2tf32(o[nd][2] * inv1)),
                            __uint_as_float(f2tf32(o[nd][3] * inv1)));
    }
}

// ---------------------------------------------------------------------------
extern "C" void kernel_launch(void* const* d_in, const int* in_sizes, int n_in,
                              void* d_out, int out_size)
{
    const float* x     = (const float*)d_in[0];
    const float* mask  = (const float*)d_in[1];
    const float* table = (const float*)d_in[2];
    const float* qkvw  = (const float*)d_in[3];
    const float* qkvb  = (const float*)d_in[4];
    const float* projw = (const float*)d_in[5];
    const float* projb = (const float*)d_in[6];
    const int*   relix = (const int*)d_in[7];
    float* out = (float*)d_out;

    const int gemm_smem = GEMM_SMEM_FLOATS * 4;
    const int attn_smem = ATTN_SMEM_FLOATS * 4;

    cudaFuncSetAttribute((void*)gemm_mma<true>,
                         cudaFuncAttributeMaxDynamicSharedMemorySize, gemm_smem);
    cudaFuncSetAttribute((void*)gemm_mma<false>,
                         cudaFuncAttributeMaxDynamicSharedMemorySize, gemm_smem);
    cudaFuncSetAttribute((void*)attn_mma,
                         cudaFuncAttributeMaxDynamicSharedMemorySize, attn_smem);

    bm_kernel<<<(64 * NHEAD * SEQ * 56 + 255) / 256, 256>>>(table, mask, relix);
    wprep_kernel<<<(QKV_COLS * KD + 255) / 256, 256>>>(qkvw, qkvb, projw);

    // QKV: M=200704, N=576. N-tile fast-varying -> A-tile sharers co-resident.
    gemm_mma<true><<<dim3(6, MROWS / 128), 128, gemm_smem>>>(
        x, nullptr, nullptr, QKV_COLS);

    attn_mma<<<dim3(B_WIN, NHEAD), 128, attn_smem>>>();

    // Proj: M=200704, N=192. Same N-fast ordering.
    gemm_mma<false><<<dim3(2, MROWS / 128), 128, gemm_smem>>>(
        nullptr, projb, out, CDIM);
}

// round 15
// speedup vs baseline: 1.4211x; 1.2637x over previous
#include <cuda_runtime.h>
#include <cuda_fp16.h>
#include <cstdint>

// ---------------- problem constants ----------------
#define B_WIN    4096
#define SEQ      49
#define CDIM     192
#define NHEAD    6
#define HDIM     32
#define KD       192
#define QKV_COLS 576
#define MROWS    200704       // B_WIN * SEQ

// ---------------- scratch (__device__ globals, allocation-free) -------------
__device__ __half g_qkv_h [(size_t)B_WIN * SEQ * QKV_COLS];
__device__ __half g_attn_h[(size_t)B_WIN * SEQ * CDIM];
__device__ float  g_bm  [64 * NHEAD * SEQ * 56];   // fused bias+mask (f32)
__device__ __half g_wqkv_h [QKV_COLS * KD];        // fp16(s*W)
__device__ float  g_bqkv [QKV_COLS];               // s*bias (f32)
__device__ __half g_wproj_h[CDIM * KD];            // fp16(W)

__device__ __forceinline__ uint32_t pack_h2(float lo, float hi) {
    uint32_t r;
    asm("cvt.rn.f16x2.f32 %0, %1, %2;" : "=r"(r) : "f"(hi), "f"(lo));
    return r;
}

__device__ __forceinline__ void mma_h(float* d, uint32_t a0, uint32_t a1,
                                      uint32_t a2, uint32_t a3,
                                      uint32_t b0, uint32_t b1) {
    asm volatile(
        "mma.sync.aligned.m16n8k16.row.col.f32.f16.f16.f32 "
        "{%0,%1,%2,%3}, {%4,%5,%6,%7}, {%8,%9}, {%0,%1,%2,%3};"
        : "+f"(d[0]), "+f"(d[1]), "+f"(d[2]), "+f"(d[3])
        : "r"(a0), "r"(a1), "r"(a2), "r"(a3), "r"(b0), "r"(b1));
}

__device__ __forceinline__ void cp16(uint32_t smem_addr, const void* gptr) {
    asm volatile("cp.async.cg.shared.global [%0], [%1], 16;"
                 :: "r"(smem_addr), "l"(gptr) : "memory");
}
#define CP_COMMIT() asm volatile("cp.async.commit_group;" ::: "memory")
#define CP_WAIT(n)  asm volatile("cp.async.wait_group %0;" :: "n"(n) : "memory")

// ---------------------------------------------------------------------------
// K0a: fused bias+mask table: g_bm[w][h][n][m] (m padded to 56 with -1e30)
// ---------------------------------------------------------------------------
__global__ void bm_kernel(const float* __restrict__ table,
                          const float* __restrict__ mask,
                          const int* __restrict__ rel_index)
{
    int i = blockIdx.x * blockDim.x + threadIdx.x;
    if (i >= 64 * NHEAD * SEQ * 56) return;
    int m = i % 56; int t = i / 56;
    int n = t % SEQ; t /= SEQ;
    int h = t % NHEAD; int w = t / NHEAD;
    float v = -1e30f;
    if (m < SEQ)
        v = table[rel_index[n * SEQ + m] * NHEAD + h]
          + mask[((size_t)w * SEQ + n) * SEQ + m];
    g_bm[i] = v;
}

// ---------------------------------------------------------------------------
// K0b: weight prep — fp16 weights (q rows pre-scaled), f32 scaled bias.
// ---------------------------------------------------------------------------
__global__ void wprep_kernel(const float* __restrict__ qkvw,
                             const float* __restrict__ qkvb,
                             const float* __restrict__ projw)
{
    const float qs = 0.17677669529663687f;   // 1/sqrt(32)
    int i = blockIdx.x * blockDim.x + threadIdx.x;
    if (i < QKV_COLS * KD) {
        float w = qkvw[i];
        if (i < CDIM * KD) w *= qs;          // q rows are the first 192
        g_wqkv_h[i] = __float2half_rn(w);
    }
    if (i < CDIM * KD)
        g_wproj_h[i] = __float2half_rn(projw[i]);
    if (i < QKV_COLS) {
        float b = qkvb[i];
        if (i < CDIM) b *= qs;
        g_bqkv[i] = b;
    }
}

// ---------------------------------------------------------------------------
// f16 HMMA GEMM: 128 thr (4 warps), CTA 128x96, warp 64x48, k-tile 32,
//   m16n8k16 MMAs (48/k-tile), 2-stage cp.async ring, 3 CTAs/SM.
//   PHASE1: A = x (f32 SMEM, LDS.64+cvt to half2), B = g_wqkv_h, out half.
//  !PHASE1: A = g_attn_h (half SMEM, raw LDS), B = g_wproj_h, out f32.
//   Dynamic SMEM must ALSO cover the 128x100 f32 epilogue stage (51200 B).
// ---------------------------------------------------------------------------
#define A1_BYTES 18432u                 // 128*36 f32
#define A2_BYTES 10240u                 // 128*40 half
#define B_BYTES  7680u                  // 96*40 half
#define STAGE1 (A1_BYTES + B_BYTES)     // 26112
#define STAGE2 (A2_BYTES + B_BYTES)     // 17920
#define EPI_BYTES 51200u                // 128*100 f32 epilogue stage
#define SMEM1 (2u*STAGE1)               // 52224  (>= EPI_BYTES)
#define SMEM2 EPI_BYTES                 // 51200  (>= 2*STAGE2 = 35840)

template<bool PHASE1>
__global__ void __launch_bounds__(128, 3)
gemm_mma(const float* __restrict__ Ain, const float* __restrict__ bias_in,
         float* __restrict__ Oin, int Ncols)
{
    extern __shared__ char smem[];
    __shared__ float bias_s[96];

    constexpr uint32_t A_BYTES = PHASE1 ? A1_BYTES : A2_BYTES;
    constexpr uint32_t STAGE_B = A_BYTES + B_BYTES;

    const __half* Wh  = PHASE1 ? g_wqkv_h : g_wproj_h;
    const float*  bias = PHASE1 ? g_bqkv : bias_in;

    const int tid  = threadIdx.x;
    const int wid  = tid >> 5;
    const int lane = tid & 31;
    const int gid  = lane >> 2;
    const int tig  = lane & 3;
    const size_t m0 = (size_t)blockIdx.y * 128;
    const int    n0 = blockIdx.x * 96;
    const int    wm = (wid >> 1) * 64;
    const int    wn = (wid & 1) * 48;

    if (tid < 24) ((float4*)bias_s)[tid] = ((const float4*)(bias + n0))[tid];

    const uint32_t smem_u32 = (uint32_t)__cvta_generic_to_shared(smem);

    auto cp_stage = [&](int kt, int buf) {
        const int k0 = kt * 32;
        const uint32_t sbase = smem_u32 + (uint32_t)buf * STAGE_B;
        if (PHASE1) {
            const int ra = tid >> 3, qa = tid & 7;
            #pragma unroll
            for (int i = 0; i < 8; ++i) {
                int r = ra + i * 16;
                cp16(sbase + (uint32_t)(r * 36 + qa * 4) * 4u,
                     Ain + (m0 + r) * (size_t)KD + k0 + qa * 4);
            }
        } else {
            const int ra = tid >> 2, qa = tid & 3;
            #pragma unroll
            for (int i = 0; i < 4; ++i) {
                int r = ra + i * 32;
                cp16(sbase + (uint32_t)(r * 80 + qa * 16),
                     g_attn_h + (m0 + r) * (size_t)KD + k0 + qa * 8);
            }
        }
        const int rb = tid >> 2, qb = tid & 3;
        const uint32_t bbase = sbase + A_BYTES;
        #pragma unroll
        for (int i = 0; i < 3; ++i) {
            int r = rb + i * 32;
            cp16(bbase + (uint32_t)(r * 80 + qb * 16),
                 Wh + (size_t)(n0 + r) * KD + k0 + qb * 8);
        }
        CP_COMMIT();
    };

    float acc[4][6][4] = {};

    cp_stage(0, 0);
    CP_WAIT(0);
    __syncthreads();

    #pragma unroll 1
    for (int kt = 0; kt < 6; ++kt) {
        const int buf = kt & 1;
        if (kt < 5) cp_stage(kt + 1, buf ^ 1);

        const float*    Asf = (const float*)(smem + buf * STAGE_B);
        const uint32_t* Ash = (const uint32_t*)(smem + buf * STAGE_B);
        const uint32_t* Bsh = (const uint32_t*)(smem + buf * STAGE_B + A_BYTES);

        #pragma unroll
        for (int ks = 0; ks < 2; ++ks) {
            uint32_t a[4][4];
            #pragma unroll
            for (int mi = 0; mi < 4; ++mi) {
                int r = wm + mi * 16 + gid;
                if (PHASE1) {
                    float2 x0 = *(const float2*)(Asf + r * 36 + ks * 16 + 2 * tig);
                    float2 x1 = *(const float2*)(Asf + (r + 8) * 36 + ks * 16 + 2 * tig);
                    float2 x2 = *(const float2*)(Asf + r * 36 + ks * 16 + 2 * tig + 8);
                    float2 x3 = *(const float2*)(Asf + (r + 8) * 36 + ks * 16 + 2 * tig + 8);
                    a[mi][0] = pack_h2(x0.x, x0.y);
                    a[mi][1] = pack_h2(x1.x, x1.y);
                    a[mi][2] = pack_h2(x2.x, x2.y);
                    a[mi][3] = pack_h2(x3.x, x3.y);
                } else {
                    int base = r * 20 + ks * 8 + tig;
                    a[mi][0] = Ash[base];
                    a[mi][1] = Ash[base + 160];
                    a[mi][2] = Ash[base + 4];
                    a[mi][3] = Ash[base + 164];
                }
            }
            uint32_t b[6][2];
            #pragma unroll
            for (int ni = 0; ni < 6; ++ni) {
                int bb = (wn + ni * 8 + gid) * 20 + ks * 8 + tig;
                b[ni][0] = Bsh[bb];
                b[ni][1] = Bsh[bb + 4];
            }
            #pragma unroll
            for (int mi = 0; mi < 4; ++mi)
                #pragma unroll
                for (int ni = 0; ni < 6; ++ni)
                    mma_h(acc[mi][ni], a[mi][0], a[mi][1], a[mi][2], a[mi][3],
                          b[ni][0], b[ni][1]);
        }

        if (kt < 5) CP_WAIT(0);
        __syncthreads();
    }

    // ---- epilogue: stage f32 to SMEM (stride 100), then coalesced STG ----
    float* stage = (float*)smem;        // 51200 B, covered by SMEM1/SMEM2
    #pragma unroll
    for (int mi = 0; mi < 4; ++mi) {
        int row0 = wm + mi * 16 + gid;
        #pragma unroll
        for (int ni = 0; ni < 6; ++ni) {
            int col0 = wn + ni * 8 + 2 * tig;
            *(float2*)(stage + row0 * 100 + col0)       = make_float2(acc[mi][ni][0], acc[mi][ni][1]);
            *(float2*)(stage + (row0 + 8) * 100 + col0) = make_float2(acc[mi][ni][2], acc[mi][ni][3]);
        }
    }
    __syncthreads();

    #pragma unroll
    for (int i = 0; i < 24; ++i) {
        int idx = tid + i * 128;
        int row = idx / 24, c4 = idx - row * 24;
        float4 v  = *(float4*)(stage + row * 100 + c4 * 4);
        float4 bv = *(float4*)(bias_s + c4 * 4);
        float4 o;
        o.x = v.x + bv.x; o.y = v.y + bv.y; o.z = v.z + bv.z; o.w = v.w + bv.w;
        if (PHASE1) {
            uint2 hv = make_uint2(pack_h2(o.x, o.y), pack_h2(o.z, o.w));
            *(uint2*)(g_qkv_h + (m0 + row) * (size_t)QKV_COLS + n0 + c4 * 4) = hv;
        } else {
            *(float4*)(Oin + (m0 + row) * (size_t)Ncols + n0 + c4 * 4) = o;
        }
    }
}

// ---------------------------------------------------------------------------
// K2: f16 tensor-core attention. One block per (window, head), 128 thr.
// QK: m16n8k16 (14 MMAs/warp). P staged per-warp in SMEM as half2
// (no cross-lane shuffles). V stored transposed for PV b-frags. PV: 16 MMAs.
// ---------------------------------------------------------------------------
__global__ void __launch_bounds__(128)
attn_mma()
{
    __shared__ __align__(16) __half qs [49 * 40];
    __shared__ __align__(16) __half ks_s[56 * 40];
    __shared__ __align__(16) __half vt [32 * 72];   // [col][key], keys padded 64
    __shared__ __align__(16) __half Ps [64 * 72];   // per-warp 16x72 slabs

    const int b = blockIdx.x;
    const int h = blockIdx.y;
    const int tid = threadIdx.x;
    const __half* base = g_qkv_h + (size_t)b * SEQ * QKV_COLS;

    // zero pads first (avoid racing with fills)
    if (tid < 35) ((uint4*)(ks_s + 49 * 40))[tid] = make_uint4(0, 0, 0, 0);
    for (int i = tid; i < 288; i += 128) ((uint4*)vt)[i] = make_uint4(0, 0, 0, 0);
    __syncthreads();

    for (int i = tid; i < 196; i += 128) {
        int n = i >> 2, c8 = (i & 3) * 8;
        *(uint4*)(qs + n * 40 + c8)   = *(const uint4*)(base + n * QKV_COLS + h * HDIM + c8);
        *(uint4*)(ks_s + n * 40 + c8) = *(const uint4*)(base + n * QKV_COLS + CDIM + h * HDIM + c8);
        uint4 v = *(const uint4*)(base + n * QKV_COLS + 2 * CDIM + h * HDIM + c8);
        __half va[8];
        *(uint4*)va = v;
        #pragma unroll
        for (int j = 0; j < 8; ++j) vt[(c8 + j) * 72 + n] = va[j];
    }
    __syncthreads();

    const int lane = tid & 31, w = tid >> 5;
    const int gid = lane >> 2, tig = lane & 3;
    const int row0 = w * 16 + gid, row1 = row0 + 8;
    const int r0c = min(row0, 48), r1c = min(row1, 48);

    // ---- S = Q K^T (f16 k16) ----
    float c[7][4] = {};
    #pragma unroll
    for (int ks = 0; ks < 2; ++ks) {
        const int ko = ks * 16;
        uint32_t a0 = *(const uint32_t*)(qs + r0c * 40 + ko + 2 * tig);
        uint32_t a1 = *(const uint32_t*)(qs + r1c * 40 + ko + 2 * tig);
        uint32_t a2 = *(const uint32_t*)(qs + r0c * 40 + ko + 2 * tig + 8);
        uint32_t a3 = *(const uint32_t*)(qs + r1c * 40 + ko + 2 * tig + 8);
        #pragma unroll
        for (int nt = 0; nt < 7; ++nt) {
            int kr = nt * 8 + gid;
            uint32_t b0 = *(const uint32_t*)(ks_s + kr * 40 + ko + 2 * tig);
            uint32_t b1 = *(const uint32_t*)(ks_s + kr * 40 + ko + 2 * tig + 8);
            mma_h(c[nt], a0, a1, a2, a3, b0, b1);
        }
    }

    // ---- add fused bias+mask ----
    const float* bmp = g_bm + ((size_t)((b & 63) * NHEAD + h)) * (SEQ * 56);
    #pragma unroll
    for (int nt = 0; nt < 7; ++nt) {
        float2 bm0 = *(const float2*)(bmp + r0c * 56 + nt * 8 + 2 * tig);
        float2 bm1 = *(const float2*)(bmp + r1c * 56 + nt * 8 + 2 * tig);
        c[nt][0] += bm0.x; c[nt][1] += bm0.y;
        c[nt][2] += bm1.x; c[nt][3] += bm1.y;
    }

    // ---- softmax (per-row, quad shuffles) ----
    float mx0 = -1e30f, mx1 = -1e30f;
    #pragma unroll
    for (int nt = 0; nt < 7; ++nt) {
        mx0 = fmaxf(mx0, fmaxf(c[nt][0], c[nt][1]));
        mx1 = fmaxf(mx1, fmaxf(c[nt][2], c[nt][3]));
    }
    mx0 = fmaxf(mx0, __shfl_xor_sync(0xffffffffu, mx0, 1));
    mx0 = fmaxf(mx0, __shfl_xor_sync(0xffffffffu, mx0, 2));
    mx1 = fmaxf(mx1, __shfl_xor_sync(0xffffffffu, mx1, 1));
    mx1 = fmaxf(mx1, __shfl_xor_sync(0xffffffffu, mx1, 2));

    float s0 = 0.f, s1 = 0.f;
    #pragma unroll
    for (int nt = 0; nt < 7; ++nt) {
        c[nt][0] = __expf(c[nt][0] - mx0); s0 += c[nt][0];
        c[nt][1] = __expf(c[nt][1] - mx0); s0 += c[nt][1];
        c[nt][2] = __expf(c[nt][2] - mx1); s1 += c[nt][2];
        c[nt][3] = __expf(c[nt][3] - mx1); s1 += c[nt][3];
    }
    s0 += __shfl_xor_sync(0xffffffffu, s0, 1);
    s0 += __shfl_xor_sync(0xffffffffu, s0, 2);
    s1 += __shfl_xor_sync(0xffffffffu, s1, 1);
    s1 += __shfl_xor_sync(0xffffffffu, s1, 2);
    const float inv0 = 1.0f / s0, inv1 = 1.0f / s1;

    // ---- stage P (unnormalized, in [0,1]) to this warp's SMEM slab ----
    __half* Pw = Ps + w * 16 * 72;
    #pragma unroll
    for (int nt = 0; nt < 7; ++nt) {
        *(uint32_t*)(Pw + gid * 72 + nt * 8 + 2 * tig)       = pack_h2(c[nt][0], c[nt][1]);
        *(uint32_t*)(Pw + (gid + 8) * 72 + nt * 8 + 2 * tig) = pack_h2(c[nt][2], c[nt][3]);
    }
    {   // zero P cols 56..63 (keys beyond pad)
        int r = lane >> 1, cz = (lane & 1) * 4;
        *(uint2*)(Pw + r * 72 + 56 + cz) = make_uint2(0, 0);
    }
    __syncwarp();

    // ---- O = P V (f16 k16) ----
    float o[4][4] = {};
    #pragma unroll
    for (int ks = 0; ks < 4; ++ks) {
        const int ko = ks * 16;
        uint32_t a0 = *(const uint32_t*)(Pw + gid * 72 + ko + 2 * tig);
        uint32_t a1 = *(const uint32_t*)(Pw + (gid + 8) * 72 + ko + 2 * tig);
        uint32_t a2 = *(const uint32_t*)(Pw + gid * 72 + ko + 2 * tig + 8);
        uint32_t a3 = *(const uint32_t*)(Pw + (gid + 8) * 72 + ko + 2 * tig + 8);
        #pragma unroll
        for (int nd = 0; nd < 4; ++nd) {
            int col = nd * 8 + gid;
            uint32_t b0 = *(const uint32_t*)(vt + col * 72 + ko + 2 * tig);
            uint32_t b1 = *(const uint32_t*)(vt + col * 72 + ko + 2 * tig + 8);
            mma_h(o[nd], a0, a1, a2, a3, b0, b1);
        }
    }

    // ---- write O as fp16, scaled by 1/rowsum ----
    __half* ob = g_attn_h + (size_t)b * SEQ * CDIM + h * HDIM;
    if (row0 < SEQ) {
        #pragma unroll
        for (int nd = 0; nd < 4; ++nd)
            *(uint32_t*)(ob + row0 * CDIM + nd * 8 + 2 * tig) =
                pack_h2(o[nd][0] * inv0, o[nd][1] * inv0);
    }
    if (row1 < SEQ) {
        #pragma unroll
        for (int nd = 0; nd < 4; ++nd)
            *(uint32_t*)(ob + row1 * CDIM + nd * 8 + 2 * tig) =
                pack_h2(o[nd][2] * inv1, o[nd][3] * inv1);
    }
}

// ---------------------------------------------------------------------------
extern "C" void kernel_launch(void* const* d_in, const int* in_sizes, int n_in,
                              void* d_out, int out_size)
{
    const float* x     = (const float*)d_in[0];
    const float* mask  = (const float*)d_in[1];
    const float* table = (const float*)d_in[2];
    const float* qkvw  = (const float*)d_in[3];
    const float* qkvb  = (const float*)d_in[4];
    const float* projw = (const float*)d_in[5];
    const float* projb = (const float*)d_in[6];
    const int*   relix = (const int*)d_in[7];
    float* out = (float*)d_out;

    cudaFuncSetAttribute((void*)gemm_mma<true>,
                         cudaFuncAttributeMaxDynamicSharedMemorySize, SMEM1);
    cudaFuncSetAttribute((void*)gemm_mma<false>,
                         cudaFuncAttributeMaxDynamicSharedMemorySize, SMEM2);

    bm_kernel<<<(64 * NHEAD * SEQ * 56 + 255) / 256, 256>>>(table, mask, relix);
    wprep_kernel<<<(QKV_COLS * KD + 255) / 256, 256>>>(qkvw, qkvb, projw);

    // QKV: M=200704, N=576. N-tile fast-varying -> A-tile sharers co-resident.
    gemm_mma<true><<<dim3(6, MROWS / 128), 128, SMEM1>>>(
        x, nullptr, nullptr, QKV_COLS);

    attn_mma<<<dim3(B_WIN, NHEAD), 128>>>();

    // Proj: M=200704, N=192. Same N-fast ordering.
    gemm_mma<false><<<dim3(2, MROWS / 128), 128, SMEM2>>>(
        nullptr, projb, out, CDIM);
}

// round 16
// speedup vs baseline: 1.5644x; 1.1008x over previous
#include <cuda_runtime.h>
#include <cuda_fp16.h>
#include <cstdint>

// ---------------- problem constants ----------------
#define B_WIN    4096
#define SEQ      49
#define CDIM     192
#define NHEAD    6
#define HDIM     32
#define KD       192
#define QKV_COLS 576
#define MROWS    200704       // B_WIN * SEQ

// ---------------- scratch (__device__ globals, allocation-free) -------------
__device__ __half g_qkv_h [(size_t)B_WIN * SEQ * QKV_COLS];
__device__ __half g_attn_h[(size_t)B_WIN * SEQ * CDIM];
__device__ float  g_bm  [64 * NHEAD * SEQ * 56];   // fused bias+mask (f32)
__device__ __half g_wqkv_h [QKV_COLS * KD];        // fp16(s*W)
__device__ float  g_bqkv [QKV_COLS];               // s*bias (f32)
__device__ __half g_wproj_h[CDIM * KD];            // fp16(W)

__device__ __forceinline__ uint32_t pack_h2(float lo, float hi) {
    uint32_t r;
    asm("cvt.rn.f16x2.f32 %0, %1, %2;" : "=r"(r) : "f"(hi), "f"(lo));
    return r;
}

__device__ __forceinline__ void mma_h(float* d, uint32_t a0, uint32_t a1,
                                      uint32_t a2, uint32_t a3,
                                      uint32_t b0, uint32_t b1) {
    asm volatile(
        "mma.sync.aligned.m16n8k16.row.col.f32.f16.f16.f32 "
        "{%0,%1,%2,%3}, {%4,%5,%6,%7}, {%8,%9}, {%0,%1,%2,%3};"
        : "+f"(d[0]), "+f"(d[1]), "+f"(d[2]), "+f"(d[3])
        : "r"(a0), "r"(a1), "r"(a2), "r"(a3), "r"(b0), "r"(b1));
}

__device__ __forceinline__ void cp16(uint32_t smem_addr, const void* gptr) {
    asm volatile("cp.async.cg.shared.global [%0], [%1], 16;"
                 :: "r"(smem_addr), "l"(gptr) : "memory");
}
#define CP_COMMIT() asm volatile("cp.async.commit_group;" ::: "memory")
#define CP_WAIT(n)  asm volatile("cp.async.wait_group %0;" :: "n"(n) : "memory")

// ---------------------------------------------------------------------------
// K0a: fused bias+mask table: g_bm[w][h][n][m] (m padded to 56 with -1e30)
// ---------------------------------------------------------------------------
__global__ void bm_kernel(const float* __restrict__ table,
                          const float* __restrict__ mask,
                          const int* __restrict__ rel_index)
{
    int i = blockIdx.x * blockDim.x + threadIdx.x;
    if (i >= 64 * NHEAD * SEQ * 56) return;
    int m = i % 56; int t = i / 56;
    int n = t % SEQ; t /= SEQ;
    int h = t % NHEAD; int w = t / NHEAD;
    float v = -1e30f;
    if (m < SEQ)
        v = table[rel_index[n * SEQ + m] * NHEAD + h]
          + mask[((size_t)w * SEQ + n) * SEQ + m];
    g_bm[i] = v;
}

// ---------------------------------------------------------------------------
// K0b: weight prep — fp16 weights (q rows pre-scaled), f32 scaled bias.
// ---------------------------------------------------------------------------
__global__ void wprep_kernel(const float* __restrict__ qkvw,
                             const float* __restrict__ qkvb,
                             const float* __restrict__ projw)
{
    const float qs = 0.17677669529663687f;   // 1/sqrt(32)
    int i = blockIdx.x * blockDim.x + threadIdx.x;
    if (i < QKV_COLS * KD) {
        float w = qkvw[i];
        if (i < CDIM * KD) w *= qs;          // q rows are the first 192
        g_wqkv_h[i] = __float2half_rn(w);
    }
    if (i < CDIM * KD)
        g_wproj_h[i] = __float2half_rn(projw[i]);
    if (i < QKV_COLS) {
        float b = qkvb[i];
        if (i < CDIM) b *= qs;
        g_bqkv[i] = b;
    }
}

// ---------------------------------------------------------------------------
// f16 HMMA GEMM (R15, unchanged): 128 thr, CTA 128x96, warp 64x48, k-tile 32,
//   2-stage cp.async ring, 3 CTAs/SM. Dyn SMEM covers the 51200 B epilogue.
// ---------------------------------------------------------------------------
#define A1_BYTES 18432u                 // 128*36 f32
#define A2_BYTES 10240u                 // 128*40 half
#define B_BYTES  7680u                  // 96*40 half
#define STAGE1 (A1_BYTES + B_BYTES)     // 26112
#define STAGE2 (A2_BYTES + B_BYTES)     // 17920
#define EPI_BYTES 51200u                // 128*100 f32 epilogue stage
#define SMEM1 (2u*STAGE1)               // 52224  (>= EPI_BYTES)
#define SMEM2 EPI_BYTES                 // 51200  (>= 2*STAGE2 = 35840)

template<bool PHASE1>
__global__ void __launch_bounds__(128, 3)
gemm_mma(const float* __restrict__ Ain, const float* __restrict__ bias_in,
         float* __restrict__ Oin, int Ncols)
{
    extern __shared__ char smem[];
    __shared__ float bias_s[96];

    constexpr uint32_t A_BYTES = PHASE1 ? A1_BYTES : A2_BYTES;
    constexpr uint32_t STAGE_B = A_BYTES + B_BYTES;

    const __half* Wh  = PHASE1 ? g_wqkv_h : g_wproj_h;
    const float*  bias = PHASE1 ? g_bqkv : bias_in;

    const int tid  = threadIdx.x;
    const int wid  = tid >> 5;
    const int lane = tid & 31;
    const int gid  = lane >> 2;
    const int tig  = lane & 3;
    const size_t m0 = (size_t)blockIdx.y * 128;
    const int    n0 = blockIdx.x * 96;
    const int    wm = (wid >> 1) * 64;
    const int    wn = (wid & 1) * 48;

    if (tid < 24) ((float4*)bias_s)[tid] = ((const float4*)(bias + n0))[tid];

    const uint32_t smem_u32 = (uint32_t)__cvta_generic_to_shared(smem);

    auto cp_stage = [&](int kt, int buf) {
        const int k0 = kt * 32;
        const uint32_t sbase = smem_u32 + (uint32_t)buf * STAGE_B;
        if (PHASE1) {
            const int ra = tid >> 3, qa = tid & 7;
            #pragma unroll
            for (int i = 0; i < 8; ++i) {
                int r = ra + i * 16;
                cp16(sbase + (uint32_t)(r * 36 + qa * 4) * 4u,
                     Ain + (m0 + r) * (size_t)KD + k0 + qa * 4);
            }
        } else {
            const int ra = tid >> 2, qa = tid & 3;
            #pragma unroll
            for (int i = 0; i < 4; ++i) {
                int r = ra + i * 32;
                cp16(sbase + (uint32_t)(r * 80 + qa * 16),
                     g_attn_h + (m0 + r) * (size_t)KD + k0 + qa * 8);
            }
        }
        const int rb = tid >> 2, qb = tid & 3;
        const uint32_t bbase = sbase + A_BYTES;
        #pragma unroll
        for (int i = 0; i < 3; ++i) {
            int r = rb + i * 32;
            cp16(bbase + (uint32_t)(r * 80 + qb * 16),
                 Wh + (size_t)(n0 + r) * KD + k0 + qb * 8);
        }
        CP_COMMIT();
    };

    float acc[4][6][4] = {};

    cp_stage(0, 0);
    CP_WAIT(0);
    __syncthreads();

    #pragma unroll 1
    for (int kt = 0; kt < 6; ++kt) {
        const int buf = kt & 1;
        if (kt < 5) cp_stage(kt + 1, buf ^ 1);

        const float*    Asf = (const float*)(smem + buf * STAGE_B);
        const uint32_t* Ash = (const uint32_t*)(smem + buf * STAGE_B);
        const uint32_t* Bsh = (const uint32_t*)(smem + buf * STAGE_B + A_BYTES);

        #pragma unroll
        for (int ks = 0; ks < 2; ++ks) {
            uint32_t a[4][4];
            #pragma unroll
            for (int mi = 0; mi < 4; ++mi) {
                int r = wm + mi * 16 + gid;
                if (PHASE1) {
                    float2 x0 = *(const float2*)(Asf + r * 36 + ks * 16 + 2 * tig);
                    float2 x1 = *(const float2*)(Asf + (r + 8) * 36 + ks * 16 + 2 * tig);
                    float2 x2 = *(const float2*)(Asf + r * 36 + ks * 16 + 2 * tig + 8);
                    float2 x3 = *(const float2*)(Asf + (r + 8) * 36 + ks * 16 + 2 * tig + 8);
                    a[mi][0] = pack_h2(x0.x, x0.y);
                    a[mi][1] = pack_h2(x1.x, x1.y);
                    a[mi][2] = pack_h2(x2.x, x2.y);
                    a[mi][3] = pack_h2(x3.x, x3.y);
                } else {
                    int base = r * 20 + ks * 8 + tig;
                    a[mi][0] = Ash[base];
                    a[mi][1] = Ash[base + 160];
                    a[mi][2] = Ash[base + 4];
                    a[mi][3] = Ash[base + 164];
                }
            }
            uint32_t b[6][2];
            #pragma unroll
            for (int ni = 0; ni < 6; ++ni) {
                int bb = (wn + ni * 8 + gid) * 20 + ks * 8 + tig;
                b[ni][0] = Bsh[bb];
                b[ni][1] = Bsh[bb + 4];
            }
            #pragma unroll
            for (int mi = 0; mi < 4; ++mi)
                #pragma unroll
                for (int ni = 0; ni < 6; ++ni)
                    mma_h(acc[mi][ni], a[mi][0], a[mi][1], a[mi][2], a[mi][3],
                          b[ni][0], b[ni][1]);
        }

        if (kt < 5) CP_WAIT(0);
        __syncthreads();
    }

    // ---- epilogue: stage f32 to SMEM (stride 100), then coalesced STG ----
    float* stage = (float*)smem;
    #pragma unroll
    for (int mi = 0; mi < 4; ++mi) {
        int row0 = wm + mi * 16 + gid;
        #pragma unroll
        for (int ni = 0; ni < 6; ++ni) {
            int col0 = wn + ni * 8 + 2 * tig;
            *(float2*)(stage + row0 * 100 + col0)       = make_float2(acc[mi][ni][0], acc[mi][ni][1]);
            *(float2*)(stage + (row0 + 8) * 100 + col0) = make_float2(acc[mi][ni][2], acc[mi][ni][3]);
        }
    }
    __syncthreads();

    #pragma unroll
    for (int i = 0; i < 24; ++i) {
        int idx = tid + i * 128;
        int row = idx / 24, c4 = idx - row * 24;
        float4 v  = *(float4*)(stage + row * 100 + c4 * 4);
        float4 bv = *(float4*)(bias_s + c4 * 4);
        float4 o;
        o.x = v.x + bv.x; o.y = v.y + bv.y; o.z = v.z + bv.z; o.w = v.w + bv.w;
        if (PHASE1) {
            uint2 hv = make_uint2(pack_h2(o.x, o.y), pack_h2(o.z, o.w));
            *(uint2*)(g_qkv_h + (m0 + row) * (size_t)QKV_COLS + n0 + c4 * 4) = hv;
        } else {
            *(float4*)(Oin + (m0 + row) * (size_t)Ncols + n0 + c4 * 4) = o;
        }
    }
}

// ---------------------------------------------------------------------------
// K2: f16 tensor-core attention, NO P staging. One block per (window, head).
// Key insight: m16n8k16 QK c-frag layout == PV a-frag layout per 8-col chunk,
// so PV a-frags are in-lane pack_h2 of c pairs (no SMEM, no shuffles).
// c[7] = 0 covers padded keys 56..63. V transposed in SMEM for b-frags.
// ---------------------------------------------------------------------------
__global__ void __launch_bounds__(128)
attn_mma()
{
    __shared__ __align__(16) __half qs  [49 * 40];
    __shared__ __align__(16) __half ks_s[56 * 40];
    __shared__ __align__(16) __half vt  [32 * 72];   // [col][key], keys padded 64

    const int b = blockIdx.x;
    const int h = blockIdx.y;
    const int tid = threadIdx.x;
    const __half* base = g_qkv_h + (size_t)b * SEQ * QKV_COLS;

    // zero pads first (avoid racing with fills)
    if (tid < 35) ((uint4*)(ks_s + 49 * 40))[tid] = make_uint4(0, 0, 0, 0);
    for (int i = tid; i < 288; i += 128) ((uint4*)vt)[i] = make_uint4(0, 0, 0, 0);
    __syncthreads();

    for (int i = tid; i < 196; i += 128) {
        int n = i >> 2, c8 = (i & 3) * 8;
        *(uint4*)(qs + n * 40 + c8)   = *(const uint4*)(base + n * QKV_COLS + h * HDIM + c8);
        *(uint4*)(ks_s + n * 40 + c8) = *(const uint4*)(base + n * QKV_COLS + CDIM + h * HDIM + c8);
        uint4 v = *(const uint4*)(base + n * QKV_COLS + 2 * CDIM + h * HDIM + c8);
        __half va[8];
        *(uint4*)va = v;
        #pragma unroll
        for (int j = 0; j < 8; ++j) vt[(c8 + j) * 72 + n] = va[j];
    }
    __syncthreads();

    const int lane = tid & 31, w = tid >> 5;
    const int gid = lane >> 2, tig = lane & 3;
    const int row0 = w * 16 + gid, row1 = row0 + 8;
    const int r0c = min(row0, 48), r1c = min(row1, 48);

    // ---- S = Q K^T (f16 k16); c[7] stays zero (padded keys 56..63) ----
    float c[8][4] = {};
    #pragma unroll
    for (int ks = 0; ks < 2; ++ks) {
        const int ko = ks * 16;
        uint32_t a0 = *(const uint32_t*)(qs + r0c * 40 + ko + 2 * tig);
        uint32_t a1 = *(const uint32_t*)(qs + r1c * 40 + ko + 2 * tig);
        uint32_t a2 = *(const uint32_t*)(qs + r0c * 40 + ko + 2 * tig + 8);
        uint32_t a3 = *(const uint32_t*)(qs + r1c * 40 + ko + 2 * tig + 8);
        #pragma unroll
        for (int nt = 0; nt < 7; ++nt) {
            int kr = nt * 8 + gid;
            uint32_t b0 = *(const uint32_t*)(ks_s + kr * 40 + ko + 2 * tig);
            uint32_t b1 = *(const uint32_t*)(ks_s + kr * 40 + ko + 2 * tig + 8);
            mma_h(c[nt], a0, a1, a2, a3, b0, b1);
        }
    }

    // ---- add fused bias+mask ----
    const float* bmp = g_bm + ((size_t)((b & 63) * NHEAD + h)) * (SEQ * 56);
    #pragma unroll
    for (int nt = 0; nt < 7; ++nt) {
        float2 bm0 = *(const float2*)(bmp + r0c * 56 + nt * 8 + 2 * tig);
        float2 bm1 = *(const float2*)(bmp + r1c * 56 + nt * 8 + 2 * tig);
        c[nt][0] += bm0.x; c[nt][1] += bm0.y;
        c[nt][2] += bm1.x; c[nt][3] += bm1.y;
    }

    // ---- softmax (per-row, quad shuffles); P left unnormalized in c ----
    float mx0 = -1e30f, mx1 = -1e30f;
    #pragma unroll
    for (int nt = 0; nt < 7; ++nt) {
        mx0 = fmaxf(mx0, fmaxf(c[nt][0], c[nt][1]));
        mx1 = fmaxf(mx1, fmaxf(c[nt][2], c[nt][3]));
    }
    mx0 = fmaxf(mx0, __shfl_xor_sync(0xffffffffu, mx0, 1));
    mx0 = fmaxf(mx0, __shfl_xor_sync(0xffffffffu, mx0, 2));
    mx1 = fmaxf(mx1, __shfl_xor_sync(0xffffffffu, mx1, 1));
    mx1 = fmaxf(mx1, __shfl_xor_sync(0xffffffffu, mx1, 2));

    float s0 = 0.f, s1 = 0.f;
    #pragma unroll
    for (int nt = 0; nt < 7; ++nt) {
        c[nt][0] = __expf(c[nt][0] - mx0); s0 += c[nt][0];
        c[nt][1] = __expf(c[nt][1] - mx0); s0 += c[nt][1];
        c[nt][2] = __expf(c[nt][2] - mx1); s1 += c[nt][2];
        c[nt][3] = __expf(c[nt][3] - mx1); s1 += c[nt][3];
    }
    s0 += __shfl_xor_sync(0xffffffffu, s0, 1);
    s0 += __shfl_xor_sync(0xffffffffu, s0, 2);
    s1 += __shfl_xor_sync(0xffffffffu, s1, 1);
    s1 += __shfl_xor_sync(0xffffffffu, s1, 2);
    const float inv0 = 1.0f / s0, inv1 = 1.0f / s1;

    // ---- O = P V: a-frags packed in-lane from c (no SMEM, no shuffles) ----
    float o[4][4] = {};
    #pragma unroll
    for (int ks = 0; ks < 4; ++ks) {
        uint32_t a0 = pack_h2(c[2 * ks][0],     c[2 * ks][1]);
        uint32_t a1 = pack_h2(c[2 * ks][2],     c[2 * ks][3]);
        uint32_t a2 = pack_h2(c[2 * ks + 1][0], c[2 * ks + 1][1]);
        uint32_t a3 = pack_h2(c[2 * ks + 1][2], c[2 * ks + 1][3]);
        const int ko = ks * 16;
        #pragma unroll
        for (int nd = 0; nd < 4; ++nd) {
            int col = nd * 8 + gid;
            uint32_t b0 = *(const uint32_t*)(vt + col * 72 + ko + 2 * tig);
            uint32_t b1 = *(const uint32_t*)(vt + col * 72 + ko + 2 * tig + 8);
            mma_h(o[nd], a0, a1, a2, a3, b0, b1);
        }
    }

    // ---- write O as fp16, scaled by 1/rowsum ----
    __half* ob = g_attn_h + (size_t)b * SEQ * CDIM + h * HDIM;
    if (row0 < SEQ) {
        #pragma unroll
        for (int nd = 0; nd < 4; ++nd)
            *(uint32_t*)(ob + row0 * CDIM + nd * 8 + 2 * tig) =
                pack_h2(o[nd][0] * inv0, o[nd][1] * inv0);
    }
    if (row1 < SEQ) {
        #pragma unroll
        for (int nd = 0; nd < 4; ++nd)
            *(uint32_t*)(ob + row1 * CDIM + nd * 8 + 2 * tig) =
                pack_h2(o[nd][2] * inv1, o[nd][3] * inv1);
    }
}

// ---------------------------------------------------------------------------
extern "C" void kernel_launch(void* const* d_in, const int* in_sizes, int n_in,
                              void* d_out, int out_size)
{
    const float* x     = (const float*)d_in[0];
    const float* mask  = (const float*)d_in[1];
    const float* table = (const float*)d_in[2];
    const float* qkvw  = (const float*)d_in[3];
    const float* qkvb  = (const float*)d_in[4];
    const float* projw = (const float*)d_in[5];
    const float* projb = (const float*)d_in[6];
    const int*   relix = (const int*)d_in[7];
    float* out = (float*)d_out;

    cudaFuncSetAttribute((void*)gemm_mma<true>,
                         cudaFuncAttributeMaxDynamicSharedMemorySize, SMEM1);
    cudaFuncSetAttribute((void*)gemm_mma<false>,
                         cudaFuncAttributeMaxDynamicSharedMemorySize, SMEM2);

    bm_kernel<<<(64 * NHEAD * SEQ * 56 + 255) / 256, 256>>>(table, mask, relix);
    wprep_kernel<<<(QKV_COLS * KD + 255) / 256, 256>>>(qkvw, qkvb, projw);

    // QKV: M=200704, N=576. N-tile fast-varying -> A-tile sharers co-resident.
    gemm_mma<true><<<dim3(6, MROWS / 128), 128, SMEM1>>>(
        x, nullptr, nullptr, QKV_COLS);

    attn_mma<<<dim3(B_WIN, NHEAD), 128>>>();

    // Proj: M=200704, N=192. Same N-fast ordering.
    gemm_mma<false><<<dim3(2, MROWS / 128), 128, SMEM2>>>(
        nullptr, projb, out, CDIM);
}

// round 17
// speedup vs baseline: 1.6022x; 1.0242x over previous
#include <cuda_runtime.h>
#include <cuda_fp16.h>
#include <cstdint>

// ---------------- problem constants ----------------
#define B_WIN    4096
#define SEQ      49
#define CDIM     192
#define NHEAD    6
#define HDIM     32
#define KD       192
#define QKV_COLS 576
#define MROWS    200704       // B_WIN * SEQ

// ---------------- scratch (__device__ globals, allocation-free) -------------
__device__ __half g_qkv_h [(size_t)B_WIN * SEQ * QKV_COLS];
__device__ __half g_attn_h[(size_t)B_WIN * SEQ * CDIM];
__device__ float  g_bm  [64 * NHEAD * SEQ * 56];   // fused bias+mask (f32)
__device__ __half g_wqkv_h [QKV_COLS * KD];        // fp16(s*W)
__device__ float  g_bqkv [QKV_COLS];               // s*bias (f32)
__device__ __half g_wproj_h[CDIM * KD];            // fp16(W)

__device__ __forceinline__ uint32_t pack_h2(float lo, float hi) {
    uint32_t r;
    asm("cvt.rn.f16x2.f32 %0, %1, %2;" : "=r"(r) : "f"(hi), "f"(lo));
    return r;
}

__device__ __forceinline__ void mma_h(float* d, uint32_t a0, uint32_t a1,
                                      uint32_t a2, uint32_t a3,
                                      uint32_t b0, uint32_t b1) {
    asm volatile(
        "mma.sync.aligned.m16n8k16.row.col.f32.f16.f16.f32 "
        "{%0,%1,%2,%3}, {%4,%5,%6,%7}, {%8,%9}, {%0,%1,%2,%3};"
        : "+f"(d[0]), "+f"(d[1]), "+f"(d[2]), "+f"(d[3])
        : "r"(a0), "r"(a1), "r"(a2), "r"(a3), "r"(b0), "r"(b1));
}

__device__ __forceinline__ void ldsm_x4_t(uint32_t& r0, uint32_t& r1,
                                          uint32_t& r2, uint32_t& r3,
                                          uint32_t addr) {
    asm volatile(
        "ldmatrix.sync.aligned.m8n8.x4.trans.shared.b16 {%0,%1,%2,%3}, [%4];"
        : "=r"(r0), "=r"(r1), "=r"(r2), "=r"(r3) : "r"(addr));
}

__device__ __forceinline__ void cp16(uint32_t smem_addr, const void* gptr) {
    asm volatile("cp.async.cg.shared.global [%0], [%1], 16;"
                 :: "r"(smem_addr), "l"(gptr) : "memory");
}
#define CP_COMMIT() asm volatile("cp.async.commit_group;" ::: "memory")
#define CP_WAIT(n)  asm volatile("cp.async.wait_group %0;" :: "n"(n) : "memory")

// ---------------------------------------------------------------------------
// K0a: fused bias+mask table: g_bm[w][h][n][m] (m padded to 56 with -1e30)
// ---------------------------------------------------------------------------
__global__ void bm_kernel(const float* __restrict__ table,
                          const float* __restrict__ mask,
                          const int* __restrict__ rel_index)
{
    int i = blockIdx.x * blockDim.x + threadIdx.x;
    if (i >= 64 * NHEAD * SEQ * 56) return;
    int m = i % 56; int t = i / 56;
    int n = t % SEQ; t /= SEQ;
    int h = t % NHEAD; int w = t / NHEAD;
    float v = -1e30f;
    if (m < SEQ)
        v = table[rel_index[n * SEQ + m] * NHEAD + h]
          + mask[((size_t)w * SEQ + n) * SEQ + m];
    g_bm[i] = v;
}

// ---------------------------------------------------------------------------
// K0b: weight prep — fp16 weights (q rows pre-scaled), f32 scaled bias.
// ---------------------------------------------------------------------------
__global__ void wprep_kernel(const float* __restrict__ qkvw,
                             const float* __restrict__ qkvb,
                             const float* __restrict__ projw)
{
    const float qs = 0.17677669529663687f;   // 1/sqrt(32)
    int i = blockIdx.x * blockDim.x + threadIdx.x;
    if (i < QKV_COLS * KD) {
        float w = qkvw[i];
        if (i < CDIM * KD) w *= qs;          // q rows are the first 192
        g_wqkv_h[i] = __float2half_rn(w);
    }
    if (i < CDIM * KD)
        g_wproj_h[i] = __float2half_rn(projw[i]);
    if (i < QKV_COLS) {
        float b = qkvb[i];
        if (i < CDIM) b *= qs;
        g_bqkv[i] = b;
    }
}

// ---------------------------------------------------------------------------
// f16 HMMA GEMM (R15, unchanged): 128 thr, CTA 128x96, warp 64x48, k-tile 32,
//   2-stage cp.async ring, 3 CTAs/SM. Dyn SMEM covers the 51200 B epilogue.
// ---------------------------------------------------------------------------
#define A1_BYTES 18432u                 // 128*36 f32
#define A2_BYTES 10240u                 // 128*40 half
#define B_BYTES  7680u                  // 96*40 half
#define STAGE1 (A1_BYTES + B_BYTES)     // 26112
#define STAGE2 (A2_BYTES + B_BYTES)     // 17920
#define EPI_BYTES 51200u                // 128*100 f32 epilogue stage
#define SMEM1 (2u*STAGE1)               // 52224  (>= EPI_BYTES)
#define SMEM2 EPI_BYTES                 // 51200  (>= 2*STAGE2 = 35840)

template<bool PHASE1>
__global__ void __launch_bounds__(128, 3)
gemm_mma(const float* __restrict__ Ain, const float* __restrict__ bias_in,
         float* __restrict__ Oin, int Ncols)
{
    extern __shared__ char smem[];
    __shared__ float bias_s[96];

    constexpr uint32_t A_BYTES = PHASE1 ? A1_BYTES : A2_BYTES;
    constexpr uint32_t STAGE_B = A_BYTES + B_BYTES;

    const __half* Wh  = PHASE1 ? g_wqkv_h : g_wproj_h;
    const float*  bias = PHASE1 ? g_bqkv : bias_in;

    const int tid  = threadIdx.x;
    const int wid  = tid >> 5;
    const int lane = tid & 31;
    const int gid  = lane >> 2;
    const int tig  = lane & 3;
    const size_t m0 = (size_t)blockIdx.y * 128;
    const int    n0 = blockIdx.x * 96;
    const int    wm = (wid >> 1) * 64;
    const int    wn = (wid & 1) * 48;

    if (tid < 24) ((float4*)bias_s)[tid] = ((const float4*)(bias + n0))[tid];

    const uint32_t smem_u32 = (uint32_t)__cvta_generic_to_shared(smem);

    auto cp_stage = [&](int kt, int buf) {
        const int k0 = kt * 32;
        const uint32_t sbase = smem_u32 + (uint32_t)buf * STAGE_B;
        if (PHASE1) {
            const int ra = tid >> 3, qa = tid & 7;
            #pragma unroll
            for (int i = 0; i < 8; ++i) {
                int r = ra + i * 16;
                cp16(sbase + (uint32_t)(r * 36 + qa * 4) * 4u,
                     Ain + (m0 + r) * (size_t)KD + k0 + qa * 4);
            }
        } else {
            const int ra = tid >> 2, qa = tid & 3;
            #pragma unroll
            for (int i = 0; i < 4; ++i) {
                int r = ra + i * 32;
                cp16(sbase + (uint32_t)(r * 80 + qa * 16),
                     g_attn_h + (m0 + r) * (size_t)KD + k0 + qa * 8);
            }
        }
        const int rb = tid >> 2, qb = tid & 3;
        const uint32_t bbase = sbase + A_BYTES;
        #pragma unroll
        for (int i = 0; i < 3; ++i) {
            int r = rb + i * 32;
            cp16(bbase + (uint32_t)(r * 80 + qb * 16),
                 Wh + (size_t)(n0 + r) * KD + k0 + qb * 8);
        }
        CP_COMMIT();
    };

    float acc[4][6][4] = {};

    cp_stage(0, 0);
    CP_WAIT(0);
    __syncthreads();

    #pragma unroll 1
    for (int kt = 0; kt < 6; ++kt) {
        const int buf = kt & 1;
        if (kt < 5) cp_stage(kt + 1, buf ^ 1);

        const float*    Asf = (const float*)(smem + buf * STAGE_B);
        const uint32_t* Ash = (const uint32_t*)(smem + buf * STAGE_B);
        const uint32_t* Bsh = (const uint32_t*)(smem + buf * STAGE_B + A_BYTES);

        #pragma unroll
        for (int ks = 0; ks < 2; ++ks) {
            uint32_t a[4][4];
            #pragma unroll
            for (int mi = 0; mi < 4; ++mi) {
                int r = wm + mi * 16 + gid;
                if (PHASE1) {
                    float2 x0 = *(const float2*)(Asf + r * 36 + ks * 16 + 2 * tig);
                    float2 x1 = *(const float2*)(Asf + (r + 8) * 36 + ks * 16 + 2 * tig);
                    float2 x2 = *(const float2*)(Asf + r * 36 + ks * 16 + 2 * tig + 8);
                    float2 x3 = *(const float2*)(Asf + (r + 8) * 36 + ks * 16 + 2 * tig + 8);
                    a[mi][0] = pack_h2(x0.x, x0.y);
                    a[mi][1] = pack_h2(x1.x, x1.y);
                    a[mi][2] = pack_h2(x2.x, x2.y);
                    a[mi][3] = pack_h2(x3.x, x3.y);
                } else {
                    int base = r * 20 + ks * 8 + tig;
                    a[mi][0] = Ash[base];
                    a[mi][1] = Ash[base + 160];
                    a[mi][2] = Ash[base + 4];
                    a[mi][3] = Ash[base + 164];
                }
            }
            uint32_t b[6][2];
            #pragma unroll
            for (int ni = 0; ni < 6; ++ni) {
                int bb = (wn + ni * 8 + gid) * 20 + ks * 8 + tig;
                b[ni][0] = Bsh[bb];
                b[ni][1] = Bsh[bb + 4];
            }
            #pragma unroll
            for (int mi = 0; mi < 4; ++mi)
                #pragma unroll
                for (int ni = 0; ni < 6; ++ni)
                    mma_h(acc[mi][ni], a[mi][0], a[mi][1], a[mi][2], a[mi][3],
                          b[ni][0], b[ni][1]);
        }

        if (kt < 5) CP_WAIT(0);
        __syncthreads();
    }

    // ---- epilogue: stage f32 to SMEM (stride 100), then coalesced STG ----
    float* stage = (float*)smem;
    #pragma unroll
    for (int mi = 0; mi < 4; ++mi) {
        int row0 = wm + mi * 16 + gid;
        #pragma unroll
        for (int ni = 0; ni < 6; ++ni) {
            int col0 = wn + ni * 8 + 2 * tig;
            *(float2*)(stage + row0 * 100 + col0)       = make_float2(acc[mi][ni][0], acc[mi][ni][1]);
            *(float2*)(stage + (row0 + 8) * 100 + col0) = make_float2(acc[mi][ni][2], acc[mi][ni][3]);
        }
    }
    __syncthreads();

    #pragma unroll
    for (int i = 0; i < 24; ++i) {
        int idx = tid + i * 128;
        int row = idx / 24, c4 = idx - row * 24;
        float4 v  = *(float4*)(stage + row * 100 + c4 * 4);
        float4 bv = *(float4*)(bias_s + c4 * 4);
        float4 o;
        o.x = v.x + bv.x; o.y = v.y + bv.y; o.z = v.z + bv.z; o.w = v.w + bv.w;
        if (PHASE1) {
            uint2 hv = make_uint2(pack_h2(o.x, o.y), pack_h2(o.z, o.w));
            *(uint2*)(g_qkv_h + (m0 + row) * (size_t)QKV_COLS + n0 + c4 * 4) = hv;
        } else {
            *(float4*)(Oin + (m0 + row) * (size_t)Ncols + n0 + c4 * 4) = o;
        }
    }
}

// ---------------------------------------------------------------------------
// K2: f16 tensor-core attention v3. One block per (window, head), 128 thr.
//  - V stored ROW-major (coalesced fill, same as K); PV b-frags loaded via
//    ldmatrix.x4.trans (8 ldmatrix/thread replace 32 LDS.32 + transpose STS).
//  - PV a-frags packed in-lane from QK c-frags (R16 identity).
//  - V pad rows 49..63 zeroed (P is 0 there, keeps 0*0=0).
// ---------------------------------------------------------------------------
__global__ void __launch_bounds__(128)
attn_mma()
{
    __shared__ __align__(16) __half qs  [49 * 40];
    __shared__ __align__(16) __half ks_s[56 * 40];
    __shared__ __align__(16) __half vs  [64 * 40];   // row-major, rows 49..63 zero

    const int b = blockIdx.x;
    const int h = blockIdx.y;
    const int tid = threadIdx.x;
    const __half* base = g_qkv_h + (size_t)b * SEQ * QKV_COLS;

    // zero pads (rows >= 49; disjoint from fills below, no extra barrier)
    if (tid < 35) ((uint4*)(ks_s + 49 * 40))[tid] = make_uint4(0, 0, 0, 0);
    else if (tid < 110) ((uint4*)(vs + 49 * 40))[tid - 35] = make_uint4(0, 0, 0, 0);

    for (int i = tid; i < 196; i += 128) {
        int n = i >> 2, c8 = (i & 3) * 8;
        *(uint4*)(qs + n * 40 + c8)   = *(const uint4*)(base + n * QKV_COLS + h * HDIM + c8);
        *(uint4*)(ks_s + n * 40 + c8) = *(const uint4*)(base + n * QKV_COLS + CDIM + h * HDIM + c8);
        *(uint4*)(vs + n * 40 + c8)   = *(const uint4*)(base + n * QKV_COLS + 2 * CDIM + h * HDIM + c8);
    }
    __syncthreads();

    const int lane = tid & 31, w = tid >> 5;
    const int gid = lane >> 2, tig = lane & 3;
    const int row0 = w * 16 + gid, row1 = row0 + 8;
    const int r0c = min(row0, 48), r1c = min(row1, 48);

    // ---- S = Q K^T (f16 k16); c[7] stays zero (padded keys 56..63) ----
    float c[8][4] = {};
    #pragma unroll
    for (int ks = 0; ks < 2; ++ks) {
        const int ko = ks * 16;
        uint32_t a0 = *(const uint32_t*)(qs + r0c * 40 + ko + 2 * tig);
        uint32_t a1 = *(const uint32_t*)(qs + r1c * 40 + ko + 2 * tig);
        uint32_t a2 = *(const uint32_t*)(qs + r0c * 40 + ko + 2 * tig + 8);
        uint32_t a3 = *(const uint32_t*)(qs + r1c * 40 + ko + 2 * tig + 8);
        #pragma unroll
        for (int nt = 0; nt < 7; ++nt) {
            int kr = nt * 8 + gid;
            uint32_t b0 = *(const uint32_t*)(ks_s + kr * 40 + ko + 2 * tig);
            uint32_t b1 = *(const uint32_t*)(ks_s + kr * 40 + ko + 2 * tig + 8);
            mma_h(c[nt], a0, a1, a2, a3, b0, b1);
        }
    }

    // ---- add fused bias+mask ----
    const float* bmp = g_bm + ((size_t)((b & 63) * NHEAD + h)) * (SEQ * 56);
    #pragma unroll
    for (int nt = 0; nt < 7; ++nt) {
        float2 bm0 = *(const float2*)(bmp + r0c * 56 + nt * 8 + 2 * tig);
        float2 bm1 = *(const float2*)(bmp + r1c * 56 + nt * 8 + 2 * tig);
        c[nt][0] += bm0.x; c[nt][1] += bm0.y;
        c[nt][2] += bm1.x; c[nt][3] += bm1.y;
    }

    // ---- softmax (per-row, quad shuffles); P left unnormalized in c ----
    float mx0 = -1e30f, mx1 = -1e30f;
    #pragma unroll
    for (int nt = 0; nt < 7; ++nt) {
        mx0 = fmaxf(mx0, fmaxf(c[nt][0], c[nt][1]));
        mx1 = fmaxf(mx1, fmaxf(c[nt][2], c[nt][3]));
    }
    mx0 = fmaxf(mx0, __shfl_xor_sync(0xffffffffu, mx0, 1));
    mx0 = fmaxf(mx0, __shfl_xor_sync(0xffffffffu, mx0, 2));
    mx1 = fmaxf(mx1, __shfl_xor_sync(0xffffffffu, mx1, 1));
    mx1 = fmaxf(mx1, __shfl_xor_sync(0xffffffffu, mx1, 2));

    float s0 = 0.f, s1 = 0.f;
    #pragma unroll
    for (int nt = 0; nt < 7; ++nt) {
        c[nt][0] = __expf(c[nt][0] - mx0); s0 += c[nt][0];
        c[nt][1] = __expf(c[nt][1] - mx0); s0 += c[nt][1];
        c[nt][2] = __expf(c[nt][2] - mx1); s1 += c[nt][2];
        c[nt][3] = __expf(c[nt][3] - mx1); s1 += c[nt][3];
    }
    s0 += __shfl_xor_sync(0xffffffffu, s0, 1);
    s0 += __shfl_xor_sync(0xffffffffu, s0, 2);
    s1 += __shfl_xor_sync(0xffffffffu, s1, 1);
    s1 += __shfl_xor_sync(0xffffffffu, s1, 2);
    const float inv0 = 1.0f / s0, inv1 = 1.0f / s1;

    // ---- O = P V: a-frags in-lane from c; b-frags via ldmatrix.trans ----
    const uint32_t vs_base = (uint32_t)__cvta_generic_to_shared(vs);
    const uint32_t lrow = ((lane >> 3) & 1) * 8 + (lane & 7);   // tile k-row
    const uint32_t lcol = (lane >> 4) * 8;                      // tile n-col

    float o[4][4] = {};
    #pragma unroll
    for (int ks = 0; ks < 4; ++ks) {
        uint32_t a0 = pack_h2(c[2 * ks][0],     c[2 * ks][1]);
        uint32_t a1 = pack_h2(c[2 * ks][2],     c[2 * ks][3]);
        uint32_t a2 = pack_h2(c[2 * ks + 1][0], c[2 * ks + 1][1]);
        uint32_t a3 = pack_h2(c[2 * ks + 1][2], c[2 * ks + 1][3]);
        uint32_t addr = vs_base + ((ks * 16 + lrow) * 40 + lcol) * 2;
        uint32_t b00, b01, b10, b11, b20, b21, b30, b31;
        ldsm_x4_t(b00, b01, b10, b11, addr);        // n 0..15
        ldsm_x4_t(b20, b21, b30, b31, addr + 32);   // n 16..31
        mma_h(o[0], a0, a1, a2, a3, b00, b01);
        mma_h(o[1], a0, a1, a2, a3, b10, b11);
        mma_h(o[2], a0, a1, a2, a3, b20, b21);
        mma_h(o[3], a0, a1, a2, a3, b30, b31);
    }

    // ---- write O as fp16, scaled by 1/rowsum ----
    __half* ob = g_attn_h + (size_t)b * SEQ * CDIM + h * HDIM;
    if (row0 < SEQ) {
        #pragma unroll
        for (int nd = 0; nd < 4; ++nd)
            *(uint32_t*)(ob + row0 * CDIM + nd * 8 + 2 * tig) =
                pack_h2(o[nd][0] * inv0, o[nd][1] * inv0);
    }
    if (row1 < SEQ) {
        #pragma unroll
        for (int nd = 0; nd < 4; ++nd)
            *(uint32_t*)(ob + row1 * CDIM + nd * 8 + 2 * tig) =
                pack_h2(o[nd][2] * inv1, o[nd][3] * inv1);
    }
}

// ---------------------------------------------------------------------------
extern "C" void kernel_launch(void* const* d_in, const int* in_sizes, int n_in,
                              void* d_out, int out_size)
{
    const float* x     = (const float*)d_in[0];
    const float* mask  = (const float*)d_in[1];
    const float* table = (const float*)d_in[2];
    const float* qkvw  = (const float*)d_in[3];
    const float* qkvb  = (const float*)d_in[4];
    const float* projw = (const float*)d_in[5];
    const float* projb = (const float*)d_in[6];
    const int*   relix = (const int*)d_in[7];
    float* out = (float*)d_out;

    cudaFuncSetAttribute((void*)gemm_mma<true>,
                         cudaFuncAttributeMaxDynamicSharedMemorySize, SMEM1);
    cudaFuncSetAttribute((void*)gemm_mma<false>,
                         cudaFuncAttributeMaxDynamicSharedMemorySize, SMEM2);

    bm_kernel<<<(64 * NHEAD * SEQ * 56 + 255) / 256, 256>>>(table, mask, relix);
    wprep_kernel<<<(QKV_COLS * KD + 255) / 256, 256>>>(qkvw, qkvb, projw);

    // QKV: M=200704, N=576. N-tile fast-varying -> A-tile sharers co-resident.
    gemm_mma<true><<<dim3(6, MROWS / 128), 128, SMEM1>>>(
        x, nullptr, nullptr, QKV_COLS);

    attn_mma<<<dim3(B_WIN, NHEAD), 128>>>();

    // Proj: M=200704, N=192. Same N-fast ordering.
    gemm_mma<false><<<dim3(2, MROWS / 128), 128, SMEM2>>>(
        nullptr, projb, out, CDIM);
}